// round 6
// baseline (speedup 1.0000x reference)
#include <cuda_runtime.h>
#include <cstdint>

#define NN 50000
#define EE 600000
#define HIDD 128
#define NH 8
#define DDIM 16

// ---------------- scratch (device globals; no allocation allowed) ----------------
__device__ float g_Qh[(size_t)NN * HIDD];
__device__ float g_Kh[(size_t)NN * HIDD];
__device__ float g_Vh[(size_t)NN * HIDD];
__device__ float g_Eh[(size_t)EE * 256];   // [Ew | Eb] per edge
__device__ float g_ce[(size_t)EE * HIDD];  // conn_e / e_attn
__device__ float g_ssum[(size_t)NN * NH];
__device__ float g_agg[(size_t)NN * HIDD];
__device__ float g_row[(size_t)NN * HIDD];
__device__ float g_hpre[(size_t)NN * HIDD];
__device__ float g_h1[(size_t)NN * HIDD];
__device__ float g_mlp[(size_t)NN * 256];

__device__ __forceinline__ float to_tf32(float x) {
    float r;
    asm("cvt.rna.tf32.f32 %0, %1;" : "=f"(r) : "f"(x));
    return r;
}

__device__ __forceinline__ void mma8(float* c, const uint32_t* a, const uint32_t* b) {
    asm volatile(
        "mma.sync.aligned.m16n8k8.row.col.f32.tf32.tf32.f32 "
        "{%0,%1,%2,%3},{%4,%5,%6,%7},{%8,%9},{%0,%1,%2,%3};"
        : "+f"(c[0]), "+f"(c[1]), "+f"(c[2]), "+f"(c[3])
        : "r"(a[0]), "r"(a[1]), "r"(a[2]), "r"(a[3]), "r"(b[0]), "r"(b[1]));
}

// ---------------- TF32 tensor-core GEMM, 4 warps, warp tile 32m x 128n ----------
// Register double-buffered k-pipeline. Block tile 128x128, 128 threads.
// Each B fragment feeds 2 mma (msub 0/1) -> half the LDS bytes per FLOP vs 16m warps.
// EPI 0: C = acc (+bias)          EPI 1: C = relu(acc + bias)
// EPI 2: C = LN(resid + acc + bias)*g + b  (grid.y==1, ldc==128)
#define SMS 136
template <int KD, int EPI>
__global__ void __launch_bounds__(128) tgemm(
    const float* __restrict__ A, const float* __restrict__ W, int ldw,
    const float* __restrict__ bias, const float* __restrict__ resid,
    const float* __restrict__ lng, const float* __restrict__ lnb,
    float* __restrict__ C, int ldc, int M)
{
    __shared__ float As[16][SMS];
    __shared__ float Ws[16][SMS];

    const int t = threadIdx.x;
    const int lane = t & 31;
    const int wid = t >> 5;            // 0..3
    const int m0b = blockIdx.x * 128;
    const int n0 = blockIdx.y * 128;
    const int wm0 = wid * 32;          // warp covers 32 m-rows
    const int gr = lane >> 2;
    const int kq = lane & 3;

    float acc[2][16][4];
#pragma unroll
    for (int s = 0; s < 2; s++)
#pragma unroll
        for (int i = 0; i < 16; i++) { acc[s][i][0] = acc[s][i][1] = acc[s][i][2] = acc[s][i][3] = 0.f; }

    const int arow = t >> 2;           // 0..31
    const int acol = (t & 3) * 4;      // 0,4,8,12
    const int wrow = t >> 5;           // 0..3
    const int wcol = (t & 31) * 4;     // 0..124

    float4 aR[4], wR[4];

    // prologue: load k-chunk 0 into registers
#pragma unroll
    for (int p = 0; p < 4; p++) {
        int row = m0b + arow + p * 32;
        aR[p] = make_float4(0.f, 0.f, 0.f, 0.f);
        if (row < M) aR[p] = *(const float4*)&A[(size_t)row * KD + acol];
        int kr = wrow + p * 4;
        wR[p] = *(const float4*)&W[(size_t)kr * ldw + n0 + wcol];
    }

    for (int kt = 0; kt < KD; kt += 16) {
        __syncthreads();   // previous compute done before smem overwrite
#pragma unroll
        for (int p = 0; p < 4; p++) {
            int r = arow + p * 32;
            As[acol + 0][r] = to_tf32(aR[p].x); As[acol + 1][r] = to_tf32(aR[p].y);
            As[acol + 2][r] = to_tf32(aR[p].z); As[acol + 3][r] = to_tf32(aR[p].w);
            int kr = wrow + p * 4;
            Ws[kr][wcol + 0] = to_tf32(wR[p].x); Ws[kr][wcol + 1] = to_tf32(wR[p].y);
            Ws[kr][wcol + 2] = to_tf32(wR[p].z); Ws[kr][wcol + 3] = to_tf32(wR[p].w);
        }
        // issue next chunk's global loads early (overlap with mma below)
        if (kt + 16 < KD) {
#pragma unroll
            for (int p = 0; p < 4; p++) {
                int row = m0b + arow + p * 32;
                aR[p] = make_float4(0.f, 0.f, 0.f, 0.f);
                if (row < M) aR[p] = *(const float4*)&A[(size_t)row * KD + kt + 16 + acol];
                int kr = wrow + p * 4;
                wR[p] = *(const float4*)&W[(size_t)(kt + 16 + kr) * ldw + n0 + wcol];
            }
        }
        __syncthreads();
#pragma unroll
        for (int ks = 0; ks < 16; ks += 8) {
            uint32_t a[2][4];
#pragma unroll
            for (int s = 0; s < 2; s++) {
                int mb = wm0 + s * 16;
                a[s][0] = __float_as_uint(As[ks + kq][mb + gr]);
                a[s][1] = __float_as_uint(As[ks + kq][mb + 8 + gr]);
                a[s][2] = __float_as_uint(As[ks + 4 + kq][mb + gr]);
                a[s][3] = __float_as_uint(As[ks + 4 + kq][mb + 8 + gr]);
            }
#pragma unroll
            for (int nf = 0; nf < 16; nf++) {
                uint32_t b[2];
                b[0] = __float_as_uint(Ws[ks + kq][nf * 8 + gr]);
                b[1] = __float_as_uint(Ws[ks + 4 + kq][nf * 8 + gr]);
                mma8(acc[0][nf], a[0], b);
                mma8(acc[1][nf], a[1], b);
            }
        }
    }

    if (EPI == 0 || EPI == 1) {
#pragma unroll
        for (int s = 0; s < 2; s++)
#pragma unroll
        for (int half = 0; half < 2; half++) {
            int r = m0b + wm0 + s * 16 + gr + half * 8;
            if (r >= M) continue;
#pragma unroll
            for (int nf = 0; nf < 16; nf++) {
                int c = n0 + nf * 8 + 2 * kq;
                float v0 = acc[s][nf][half * 2 + 0];
                float v1 = acc[s][nf][half * 2 + 1];
                if (bias) { v0 += bias[c]; v1 += bias[c + 1]; }
                if (EPI == 1) { v0 = fmaxf(v0, 0.f); v1 = fmaxf(v1, 0.f); }
                *(float2*)&C[(size_t)r * ldc + c] = make_float2(v0, v1);
            }
        }
    } else {
        // LayerNorm epilogue: a row's 128 cols are held by the 4 lanes of one group.
        float v[32];
#pragma unroll
        for (int s = 0; s < 2; s++)
#pragma unroll
        for (int half = 0; half < 2; half++) {
            int r = m0b + wm0 + s * 16 + gr + half * 8;
            bool ok = (r < M);
            float sm = 0.f, s2 = 0.f;
#pragma unroll
            for (int nf = 0; nf < 16; nf++) {
                int c = nf * 8 + 2 * kq;
                float x0 = acc[s][nf][half * 2 + 0] + bias[c];
                float x1 = acc[s][nf][half * 2 + 1] + bias[c + 1];
                if (ok) {
                    float2 rr = *(const float2*)&resid[(size_t)r * 128 + c];
                    x0 += rr.x; x1 += rr.y;
                }
                v[2 * nf] = x0; v[2 * nf + 1] = x1;
                sm += x0 + x1;
                s2 += x0 * x0 + x1 * x1;
            }
#pragma unroll
            for (int off = 1; off < 4; off <<= 1) {
                sm += __shfl_xor_sync(0xffffffffu, sm, off);
                s2 += __shfl_xor_sync(0xffffffffu, s2, off);
            }
            float mean = sm * (1.f / 128.f);
            float var = s2 * (1.f / 128.f) - mean * mean;
            float rstd = rsqrtf(var + 1e-5f);
            if (ok) {
#pragma unroll
                for (int nf = 0; nf < 16; nf++) {
                    int c = nf * 8 + 2 * kq;
                    float o0 = (v[2 * nf] - mean) * rstd * lng[c] + lnb[c];
                    float o1 = (v[2 * nf + 1] - mean) * rstd * lng[c + 1] + lnb[c + 1];
                    *(float2*)&C[(size_t)r * 128 + c] = make_float2(o0, o1);
                }
            }
        }
    }
}

// ---------------- edge pass: conn_e, scores, segment accumulation ----------------
// one warp per edge. Softmax max-shift dropped (scores clipped to +-5 -> exact).
__global__ void __launch_bounds__(256) edge_kernel(const int* __restrict__ ei,
                                                   const float* __restrict__ Aw)
{
    int e = (int)((blockIdx.x * (size_t)blockDim.x + threadIdx.x) >> 5);
    int l = threadIdx.x & 31;
    if (e >= EE) return;
    int dst = ei[e];
    int src = ei[EE + e];
    int c0 = l * 4;
    int h = l >> 2;
    int dbase = (l & 3) * 4;

    float4 q = *(const float4*)&g_Qh[(size_t)dst * HIDD + c0];
    float4 kk = *(const float4*)&g_Kh[(size_t)src * HIDD + c0];
    float4 ew = *(const float4*)&g_Eh[(size_t)e * 256 + c0];
    float4 eb = *(const float4*)&g_Eh[(size_t)e * 256 + 128 + c0];
    float4 vv = *(const float4*)&g_Vh[(size_t)src * HIDD + c0];

    const float* qf = (const float*)&q;
    const float* kf = (const float*)&kk;
    const float* ewf = (const float*)&ew;
    const float* ebf = (const float*)&eb;
    const float* vf = (const float*)&vv;

    float ce[4];
    float part = 0.f;
#pragma unroll
    for (int i = 0; i < 4; i++) {
        float m = qf[i] + kf[i];
        float cc = m * ewf[i];
        float ss = sqrtf(fabsf(cc));
        ss = (cc >= 0.f) ? ss : -ss;          // signed sqrt
        float val = ss + ebf[i];
        ce[i] = fmaxf(val, 0.f);
        part += ce[i] * Aw[(dbase + i) * NH + h];
    }
    *(float4*)&g_ce[(size_t)e * HIDD + c0] = make_float4(ce[0], ce[1], ce[2], ce[3]);

    part += __shfl_xor_sync(0xffffffffu, part, 1);
    part += __shfl_xor_sync(0xffffffffu, part, 2);
    float s = fminf(fmaxf(part, -5.f), 5.f);
    float p = __expf(s);

    if ((l & 3) == 0) atomicAdd(&g_ssum[(size_t)dst * NH + h], p);
    float4 av = make_float4(vf[0] * p, vf[1] * p, vf[2] * p, vf[3] * p);
    float4 rv = make_float4(ce[0] * p, ce[1] * p, ce[2] * p, ce[3] * p);
    atomicAdd((float4*)&g_agg[(size_t)dst * HIDD + c0], av);
    atomicAdd((float4*)&g_row[(size_t)dst * HIDD + c0], rv);
}

// ---------------- node pass: normalize, rowV = row @ Bw, deg scaling ----------------
__global__ void __launch_bounds__(256) node_kernel(const float* __restrict__ Bw,
                                                   const float* __restrict__ deg_coef,
                                                   const float* __restrict__ log_deg)
{
    __shared__ float rbuf[8][HIDD];
    int n = (int)((blockIdx.x * (size_t)blockDim.x + threadIdx.x) >> 5);
    int wl = (threadIdx.x >> 5) & 7;
    int l = threadIdx.x & 31;
    if (n >= NN) return;
    int h = l >> 2;
    int c0 = l * 4;

    float rs = 1.f / (g_ssum[(size_t)n * NH + h] + 1e-16f);
    float4 a = *(const float4*)&g_agg[(size_t)n * HIDD + c0];
    float4 r = *(const float4*)&g_row[(size_t)n * HIDD + c0];
    a.x *= rs; a.y *= rs; a.z *= rs; a.w *= rs;
    r.x *= rs; r.y *= rs; r.z *= rs; r.w *= rs;
    *(float4*)&rbuf[wl][c0] = r;
    __syncwarp();

    float4 q = *(const float4*)&g_Qh[(size_t)n * HIDD + c0];
    const float* af = (const float*)&a;
    const float* qf = (const float*)&q;
    float ld = log_deg[n];

    float out[4];
#pragma unroll
    for (int i = 0; i < 4; i++) {
        int c = c0 + i;
        float rv = 0.f;
#pragma unroll
        for (int d = 0; d < DDIM; d++)
            rv = fmaf(rbuf[wl][h * DDIM + d], __ldg(&Bw[d * HIDD + c]), rv);
        float ha = qf[i] + af[i] + rv;
        out[i] = ha * (deg_coef[2 * c] + ld * deg_coef[2 * c + 1]);
    }
    *(float4*)&g_hpre[(size_t)n * HIDD + c0] = make_float4(out[0], out[1], out[2], out[3]);
}

// ---------------- launch ----------------
extern "C" void kernel_launch(void* const* d_in, const int* in_sizes, int n_in,
                              void* d_out, int out_size)
{
    const float* x        = (const float*)d_in[0];
    const float* conn     = (const float*)d_in[1];
    const float* log_deg  = (const float*)d_in[2];
    const int*   ei       = (const int*)d_in[3];
    const float* WQ       = (const float*)d_in[4];
    const float* WK       = (const float*)d_in[5];
    const float* WV       = (const float*)d_in[6];
    const float* WE       = (const float*)d_in[7];
    const float* Aw       = (const float*)d_in[8];
    const float* Bw       = (const float*)d_in[9];
    const float* Ho_w     = (const float*)d_in[10];
    const float* Ho_b     = (const float*)d_in[11];
    const float* Eo_w     = (const float*)d_in[12];
    const float* Eo_b     = (const float*)d_in[13];
    const float* deg_coef = (const float*)d_in[14];
    const float* ln1h_g   = (const float*)d_in[15];
    const float* ln1h_b   = (const float*)d_in[16];
    const float* ln1e_g   = (const float*)d_in[17];
    const float* ln1e_b   = (const float*)d_in[18];
    const float* ln2h_g   = (const float*)d_in[19];
    const float* ln2h_b   = (const float*)d_in[20];
    const float* W1       = (const float*)d_in[21];
    const float* b1       = (const float*)d_in[22];
    const float* W2       = (const float*)d_in[23];
    const float* b2       = (const float*)d_in[24];

    float* out_h = (float*)d_out;
    float* out_e = out_h + (size_t)NN * HIDD;

    float *Qh, *Kh, *Vh, *Eh, *ce, *ssum, *agg, *row, *hpre, *h1, *mlp;
    cudaGetSymbolAddress((void**)&Qh, g_Qh);
    cudaGetSymbolAddress((void**)&Kh, g_Kh);
    cudaGetSymbolAddress((void**)&Vh, g_Vh);
    cudaGetSymbolAddress((void**)&Eh, g_Eh);
    cudaGetSymbolAddress((void**)&ce, g_ce);
    cudaGetSymbolAddress((void**)&ssum, g_ssum);
    cudaGetSymbolAddress((void**)&agg, g_agg);
    cudaGetSymbolAddress((void**)&row, g_row);
    cudaGetSymbolAddress((void**)&hpre, g_hpre);
    cudaGetSymbolAddress((void**)&h1, g_h1);
    cudaGetSymbolAddress((void**)&mlp, g_mlp);

    const int gN = (NN + 127) / 128;   // 391
    const int gE = (EE + 127) / 128;   // 4688

    cudaMemsetAsync(ssum, 0, (size_t)NN * NH * sizeof(float), 0);
    cudaMemsetAsync(agg, 0, (size_t)NN * HIDD * sizeof(float), 0);
    cudaMemsetAsync(row, 0, (size_t)NN * HIDD * sizeof(float), 0);

    // Qh, Kh, Vh
    tgemm<128, 0><<<dim3(gN, 1), 128>>>(x, WQ, 128, nullptr, nullptr, nullptr, nullptr, Qh, 128, NN);
    tgemm<128, 0><<<dim3(gN, 1), 128>>>(x, WK, 128, nullptr, nullptr, nullptr, nullptr, Kh, 128, NN);
    tgemm<128, 0><<<dim3(gN, 1), 128>>>(x, WV, 128, nullptr, nullptr, nullptr, nullptr, Vh, 128, NN);
    // Eh = conn @ WE  [E,256]
    tgemm<128, 0><<<dim3(gE, 2), 128>>>(conn, WE, 256, nullptr, nullptr, nullptr, nullptr, Eh, 256, EE);

    // edge pass (conn_e + softmax-weighted segment sums)
    edge_kernel<<<(EE * 32 + 255) / 256, 256>>>(ei, Aw);
    // node pass -> h_pre
    node_kernel<<<(NN * 32 + 255) / 256, 256>>>(Bw, deg_coef, log_deg);

    // h1 = LN1h(x + hpre @ Ho_w + Ho_b)
    tgemm<128, 2><<<dim3(gN, 1), 128>>>(hpre, Ho_w, 128, Ho_b, x, ln1h_g, ln1h_b, h1, 128, NN);
    // mlp = relu(h1 @ W1 + b1)
    tgemm<128, 1><<<dim3(gN, 2), 128>>>(h1, W1, 256, b1, nullptr, nullptr, nullptr, mlp, 256, NN);
    // out_h = LN2h(h1 + mlp @ W2 + b2)
    tgemm<256, 2><<<dim3(gN, 1), 128>>>(mlp, W2, 128, b2, h1, ln2h_g, ln2h_b, out_h, 128, NN);
    // out_e = LN1e(conn + ce @ Eo_w + Eo_b)
    tgemm<128, 2><<<dim3(gE, 1), 128>>>(ce, Eo_w, 128, Eo_b, conn, ln1e_g, ln1e_b, out_e, 128, EE);
}

// round 7
// speedup vs baseline: 1.3933x; 1.3933x over previous
#include <cuda_runtime.h>
#include <cstdint>

#define NN 50000
#define EE 600000
#define HIDD 128
#define NH 8
#define DDIM 16

// ---------------- scratch (device globals; no allocation allowed) ----------------
__device__ float g_Qh[(size_t)NN * HIDD];
__device__ float g_Kh[(size_t)NN * HIDD];
__device__ float g_Vh[(size_t)NN * HIDD];
__device__ float g_Eh[(size_t)EE * 256];   // [Ew | Eb] per edge
__device__ float g_ce[(size_t)EE * HIDD];  // conn_e / e_attn
__device__ float g_ssum[(size_t)NN * NH];
__device__ float g_agg[(size_t)NN * HIDD];
__device__ float g_row[(size_t)NN * HIDD];
__device__ float g_hpre[(size_t)NN * HIDD];
__device__ float g_h1[(size_t)NN * HIDD];
__device__ float g_mlp[(size_t)NN * 256];

__device__ __forceinline__ float to_tf32(float x) {
    float r;
    asm("cvt.rna.tf32.f32 %0, %1;" : "=f"(r) : "f"(x));
    return r;
}

__device__ __forceinline__ void mma8(float* c, const uint32_t* a, const uint32_t* b) {
    asm volatile(
        "mma.sync.aligned.m16n8k8.row.col.f32.tf32.tf32.f32 "
        "{%0,%1,%2,%3},{%4,%5,%6,%7},{%8,%9},{%0,%1,%2,%3};"
        : "+f"(c[0]), "+f"(c[1]), "+f"(c[2]), "+f"(c[3])
        : "r"(a[0]), "r"(a[1]), "r"(a[2]), "r"(a[3]), "r"(b[0]), "r"(b[1]));
}

// ---------------- TF32 tensor-core GEMM: 256 thr, 8 warps in 4m x 2n grid -------
// Warp tile 32m x 64n, block tile 128x128, register double-buffered k-pipeline.
// B fragments feed 2 mma each (2 m-subtiles) -> 1/3 less LDS than 16mx128n layout,
// while acc stays 64 regs/thread so 2 CTAs/SM (16 warps) are preserved.
// EPI 0: C = acc (+bias)          EPI 1: C = relu(acc + bias)
// EPI 2: C = LN(resid + acc + bias)*g + b  (grid.y==1, ldc==128; cross-warp row
//        reduction through smem since a row spans the 2 n-warps)
#define SMS 136
template <int KD, int EPI>
__global__ void __launch_bounds__(256, 2) tgemm(
    const float* __restrict__ A, const float* __restrict__ W, int ldw,
    const float* __restrict__ bias, const float* __restrict__ resid,
    const float* __restrict__ lng, const float* __restrict__ lnb,
    float* __restrict__ C, int ldc, int M)
{
    __shared__ float As[16][SMS];
    __shared__ float Ws[16][SMS];
    __shared__ float part[128][2][2];   // [row][wn][{sum, sumsq}] for EPI 2

    const int t = threadIdx.x;
    const int lane = t & 31;
    const int wid = t >> 5;            // 0..7
    const int wn = wid & 1;            // n half (64 cols)
    const int wm = wid >> 1;           // m quarter (32 rows)
    const int m0b = blockIdx.x * 128;
    const int n0 = blockIdx.y * 128;
    const int wm0 = wm * 32;
    const int wn0 = wn * 64;
    const int gr = lane >> 2;
    const int kq = lane & 3;

    float acc[2][8][4];
#pragma unroll
    for (int s = 0; s < 2; s++)
#pragma unroll
        for (int i = 0; i < 8; i++) { acc[s][i][0] = acc[s][i][1] = acc[s][i][2] = acc[s][i][3] = 0.f; }

    const int arow = t >> 2;           // 0..63
    const int acol = (t & 3) * 4;      // 0,4,8,12
    const int wrow = t >> 5;           // 0..7
    const int wcol = (t & 31) * 4;     // 0..124

    float4 aR[2], wR[2];

    // prologue: load k-chunk 0 into registers
#pragma unroll
    for (int p = 0; p < 2; p++) {
        int row = m0b + arow + p * 64;
        aR[p] = make_float4(0.f, 0.f, 0.f, 0.f);
        if (row < M) aR[p] = *(const float4*)&A[(size_t)row * KD + acol];
        int kr = wrow + p * 8;
        wR[p] = *(const float4*)&W[(size_t)kr * ldw + n0 + wcol];
    }

    for (int kt = 0; kt < KD; kt += 16) {
        __syncthreads();   // previous compute done before smem overwrite
#pragma unroll
        for (int p = 0; p < 2; p++) {
            int r = arow + p * 64;
            As[acol + 0][r] = to_tf32(aR[p].x); As[acol + 1][r] = to_tf32(aR[p].y);
            As[acol + 2][r] = to_tf32(aR[p].z); As[acol + 3][r] = to_tf32(aR[p].w);
            int kr = wrow + p * 8;
            Ws[kr][wcol + 0] = to_tf32(wR[p].x); Ws[kr][wcol + 1] = to_tf32(wR[p].y);
            Ws[kr][wcol + 2] = to_tf32(wR[p].z); Ws[kr][wcol + 3] = to_tf32(wR[p].w);
        }
        // issue next chunk's global loads early (overlap with mma below)
        if (kt + 16 < KD) {
#pragma unroll
            for (int p = 0; p < 2; p++) {
                int row = m0b + arow + p * 64;
                aR[p] = make_float4(0.f, 0.f, 0.f, 0.f);
                if (row < M) aR[p] = *(const float4*)&A[(size_t)row * KD + kt + 16 + acol];
                int kr = wrow + p * 8;
                wR[p] = *(const float4*)&W[(size_t)(kt + 16 + kr) * ldw + n0 + wcol];
            }
        }
        __syncthreads();
#pragma unroll
        for (int ks = 0; ks < 16; ks += 8) {
            uint32_t a[2][4];
#pragma unroll
            for (int s = 0; s < 2; s++) {
                int mb = wm0 + s * 16;
                a[s][0] = __float_as_uint(As[ks + kq][mb + gr]);
                a[s][1] = __float_as_uint(As[ks + kq][mb + 8 + gr]);
                a[s][2] = __float_as_uint(As[ks + 4 + kq][mb + gr]);
                a[s][3] = __float_as_uint(As[ks + 4 + kq][mb + 8 + gr]);
            }
#pragma unroll
            for (int nf = 0; nf < 8; nf++) {
                uint32_t b[2];
                b[0] = __float_as_uint(Ws[ks + kq][wn0 + nf * 8 + gr]);
                b[1] = __float_as_uint(Ws[ks + 4 + kq][wn0 + nf * 8 + gr]);
                mma8(acc[0][nf], a[0], b);
                mma8(acc[1][nf], a[1], b);
            }
        }
    }

    if (EPI == 0 || EPI == 1) {
#pragma unroll
        for (int s = 0; s < 2; s++)
#pragma unroll
        for (int half = 0; half < 2; half++) {
            int r = m0b + wm0 + s * 16 + gr + half * 8;
            if (r >= M) continue;
#pragma unroll
            for (int nf = 0; nf < 8; nf++) {
                int c = n0 + wn0 + nf * 8 + 2 * kq;
                float v0 = acc[s][nf][half * 2 + 0];
                float v1 = acc[s][nf][half * 2 + 1];
                if (bias) { v0 += bias[c]; v1 += bias[c + 1]; }
                if (EPI == 1) { v0 = fmaxf(v0, 0.f); v1 = fmaxf(v1, 0.f); }
                *(float2*)&C[(size_t)r * ldc + c] = make_float2(v0, v1);
            }
        }
    } else {
        // EPI 2: LayerNorm with cross-warp (2 n-halves) row reduction via smem.
        float v[2][2][16];   // [s][half][16 cols owned in this n-half]
#pragma unroll
        for (int s = 0; s < 2; s++)
#pragma unroll
        for (int half = 0; half < 2; half++) {
            int r = m0b + wm0 + s * 16 + gr + half * 8;
            bool ok = (r < M);
            float sm = 0.f, s2 = 0.f;
#pragma unroll
            for (int nf = 0; nf < 8; nf++) {
                int c = wn0 + nf * 8 + 2 * kq;
                float x0 = acc[s][nf][half * 2 + 0] + bias[c];
                float x1 = acc[s][nf][half * 2 + 1] + bias[c + 1];
                if (ok) {
                    float2 rr = *(const float2*)&resid[(size_t)r * 128 + c];
                    x0 += rr.x; x1 += rr.y;
                }
                v[s][half][2 * nf] = x0; v[s][half][2 * nf + 1] = x1;
                sm += x0 + x1;
                s2 += x0 * x0 + x1 * x1;
            }
#pragma unroll
            for (int off = 1; off < 4; off <<= 1) {
                sm += __shfl_xor_sync(0xffffffffu, sm, off);
                s2 += __shfl_xor_sync(0xffffffffu, s2, off);
            }
            if (kq == 0) {
                int lr = wm0 + s * 16 + gr + half * 8;
                part[lr][wn][0] = sm;
                part[lr][wn][1] = s2;
            }
        }
        __syncthreads();
#pragma unroll
        for (int s = 0; s < 2; s++)
#pragma unroll
        for (int half = 0; half < 2; half++) {
            int lr = wm0 + s * 16 + gr + half * 8;
            int r = m0b + lr;
            if (r >= M) continue;
            float sm = part[lr][0][0] + part[lr][1][0];
            float s2 = part[lr][0][1] + part[lr][1][1];
            float mean = sm * (1.f / 128.f);
            float var = s2 * (1.f / 128.f) - mean * mean;
            float rstd = rsqrtf(var + 1e-5f);
#pragma unroll
            for (int nf = 0; nf < 8; nf++) {
                int c = wn0 + nf * 8 + 2 * kq;
                float o0 = (v[s][half][2 * nf] - mean) * rstd * lng[c] + lnb[c];
                float o1 = (v[s][half][2 * nf + 1] - mean) * rstd * lng[c + 1] + lnb[c + 1];
                *(float2*)&C[(size_t)r * 128 + c] = make_float2(o0, o1);
            }
        }
    }
}

// ---------------- edge pass: conn_e, scores, segment accumulation ----------------
// one warp per edge. Softmax max-shift dropped (scores clipped to +-5 -> exact).
__global__ void __launch_bounds__(256) edge_kernel(const int* __restrict__ ei,
                                                   const float* __restrict__ Aw)
{
    int e = (int)((blockIdx.x * (size_t)blockDim.x + threadIdx.x) >> 5);
    int l = threadIdx.x & 31;
    if (e >= EE) return;
    int dst = ei[e];
    int src = ei[EE + e];
    int c0 = l * 4;
    int h = l >> 2;
    int dbase = (l & 3) * 4;

    float4 q = *(const float4*)&g_Qh[(size_t)dst * HIDD + c0];
    float4 kk = *(const float4*)&g_Kh[(size_t)src * HIDD + c0];
    float4 ew = *(const float4*)&g_Eh[(size_t)e * 256 + c0];
    float4 eb = *(const float4*)&g_Eh[(size_t)e * 256 + 128 + c0];
    float4 vv = *(const float4*)&g_Vh[(size_t)src * HIDD + c0];

    const float* qf = (const float*)&q;
    const float* kf = (const float*)&kk;
    const float* ewf = (const float*)&ew;
    const float* ebf = (const float*)&eb;
    const float* vf = (const float*)&vv;

    float ce[4];
    float part = 0.f;
#pragma unroll
    for (int i = 0; i < 4; i++) {
        float m = qf[i] + kf[i];
        float cc = m * ewf[i];
        float ss = sqrtf(fabsf(cc));
        ss = (cc >= 0.f) ? ss : -ss;          // signed sqrt
        float val = ss + ebf[i];
        ce[i] = fmaxf(val, 0.f);
        part += ce[i] * Aw[(dbase + i) * NH + h];
    }
    *(float4*)&g_ce[(size_t)e * HIDD + c0] = make_float4(ce[0], ce[1], ce[2], ce[3]);

    part += __shfl_xor_sync(0xffffffffu, part, 1);
    part += __shfl_xor_sync(0xffffffffu, part, 2);
    float s = fminf(fmaxf(part, -5.f), 5.f);
    float p = __expf(s);

    if ((l & 3) == 0) atomicAdd(&g_ssum[(size_t)dst * NH + h], p);
    float4 av = make_float4(vf[0] * p, vf[1] * p, vf[2] * p, vf[3] * p);
    float4 rv = make_float4(ce[0] * p, ce[1] * p, ce[2] * p, ce[3] * p);
    atomicAdd((float4*)&g_agg[(size_t)dst * HIDD + c0], av);
    atomicAdd((float4*)&g_row[(size_t)dst * HIDD + c0], rv);
}

// ---------------- node pass: normalize, rowV = row @ Bw, deg scaling ----------------
__global__ void __launch_bounds__(256) node_kernel(const float* __restrict__ Bw,
                                                   const float* __restrict__ deg_coef,
                                                   const float* __restrict__ log_deg)
{
    __shared__ float rbuf[8][HIDD];
    int n = (int)((blockIdx.x * (size_t)blockDim.x + threadIdx.x) >> 5);
    int wl = (threadIdx.x >> 5) & 7;
    int l = threadIdx.x & 31;
    if (n >= NN) return;
    int h = l >> 2;
    int c0 = l * 4;

    float rs = 1.f / (g_ssum[(size_t)n * NH + h] + 1e-16f);
    float4 a = *(const float4*)&g_agg[(size_t)n * HIDD + c0];
    float4 r = *(const float4*)&g_row[(size_t)n * HIDD + c0];
    a.x *= rs; a.y *= rs; a.z *= rs; a.w *= rs;
    r.x *= rs; r.y *= rs; r.z *= rs; r.w *= rs;
    *(float4*)&rbuf[wl][c0] = r;
    __syncwarp();

    float4 q = *(const float4*)&g_Qh[(size_t)n * HIDD + c0];
    const float* af = (const float*)&a;
    const float* qf = (const float*)&q;
    float ld = log_deg[n];

    float out[4];
#pragma unroll
    for (int i = 0; i < 4; i++) {
        int c = c0 + i;
        float rv = 0.f;
#pragma unroll
        for (int d = 0; d < DDIM; d++)
            rv = fmaf(rbuf[wl][h * DDIM + d], __ldg(&Bw[d * HIDD + c]), rv);
        float ha = qf[i] + af[i] + rv;
        out[i] = ha * (deg_coef[2 * c] + ld * deg_coef[2 * c + 1]);
    }
    *(float4*)&g_hpre[(size_t)n * HIDD + c0] = make_float4(out[0], out[1], out[2], out[3]);
}

// ---------------- launch ----------------
extern "C" void kernel_launch(void* const* d_in, const int* in_sizes, int n_in,
                              void* d_out, int out_size)
{
    const float* x        = (const float*)d_in[0];
    const float* conn     = (const float*)d_in[1];
    const float* log_deg  = (const float*)d_in[2];
    const int*   ei       = (const int*)d_in[3];
    const float* WQ       = (const float*)d_in[4];
    const float* WK       = (const float*)d_in[5];
    const float* WV       = (const float*)d_in[6];
    const float* WE       = (const float*)d_in[7];
    const float* Aw       = (const float*)d_in[8];
    const float* Bw       = (const float*)d_in[9];
    const float* Ho_w     = (const float*)d_in[10];
    const float* Ho_b     = (const float*)d_in[11];
    const float* Eo_w     = (const float*)d_in[12];
    const float* Eo_b     = (const float*)d_in[13];
    const float* deg_coef = (const float*)d_in[14];
    const float* ln1h_g   = (const float*)d_in[15];
    const float* ln1h_b   = (const float*)d_in[16];
    const float* ln1e_g   = (const float*)d_in[17];
    const float* ln1e_b   = (const float*)d_in[18];
    const float* ln2h_g   = (const float*)d_in[19];
    const float* ln2h_b   = (const float*)d_in[20];
    const float* W1       = (const float*)d_in[21];
    const float* b1       = (const float*)d_in[22];
    const float* W2       = (const float*)d_in[23];
    const float* b2       = (const float*)d_in[24];

    float* out_h = (float*)d_out;
    float* out_e = out_h + (size_t)NN * HIDD;

    float *Qh, *Kh, *Vh, *Eh, *ce, *ssum, *agg, *row, *hpre, *h1, *mlp;
    cudaGetSymbolAddress((void**)&Qh, g_Qh);
    cudaGetSymbolAddress((void**)&Kh, g_Kh);
    cudaGetSymbolAddress((void**)&Vh, g_Vh);
    cudaGetSymbolAddress((void**)&Eh, g_Eh);
    cudaGetSymbolAddress((void**)&ce, g_ce);
    cudaGetSymbolAddress((void**)&ssum, g_ssum);
    cudaGetSymbolAddress((void**)&agg, g_agg);
    cudaGetSymbolAddress((void**)&row, g_row);
    cudaGetSymbolAddress((void**)&hpre, g_hpre);
    cudaGetSymbolAddress((void**)&h1, g_h1);
    cudaGetSymbolAddress((void**)&mlp, g_mlp);

    const int gN = (NN + 127) / 128;   // 391
    const int gE = (EE + 127) / 128;   // 4688

    cudaMemsetAsync(ssum, 0, (size_t)NN * NH * sizeof(float), 0);
    cudaMemsetAsync(agg, 0, (size_t)NN * HIDD * sizeof(float), 0);
    cudaMemsetAsync(row, 0, (size_t)NN * HIDD * sizeof(float), 0);

    // Qh, Kh, Vh
    tgemm<128, 0><<<dim3(gN, 1), 256>>>(x, WQ, 128, nullptr, nullptr, nullptr, nullptr, Qh, 128, NN);
    tgemm<128, 0><<<dim3(gN, 1), 256>>>(x, WK, 128, nullptr, nullptr, nullptr, nullptr, Kh, 128, NN);
    tgemm<128, 0><<<dim3(gN, 1), 256>>>(x, WV, 128, nullptr, nullptr, nullptr, nullptr, Vh, 128, NN);
    // Eh = conn @ WE  [E,256]
    tgemm<128, 0><<<dim3(gE, 2), 256>>>(conn, WE, 256, nullptr, nullptr, nullptr, nullptr, Eh, 256, EE);

    // edge pass (conn_e + softmax-weighted segment sums)
    edge_kernel<<<(EE * 32 + 255) / 256, 256>>>(ei, Aw);
    // node pass -> h_pre
    node_kernel<<<(NN * 32 + 255) / 256, 256>>>(Bw, deg_coef, log_deg);

    // h1 = LN1h(x + hpre @ Ho_w + Ho_b)
    tgemm<128, 2><<<dim3(gN, 1), 256>>>(hpre, Ho_w, 128, Ho_b, x, ln1h_g, ln1h_b, h1, 128, NN);
    // mlp = relu(h1 @ W1 + b1)
    tgemm<128, 1><<<dim3(gN, 2), 256>>>(h1, W1, 256, b1, nullptr, nullptr, nullptr, mlp, 256, NN);
    // out_h = LN2h(h1 + mlp @ W2 + b2)
    tgemm<256, 2><<<dim3(gN, 1), 256>>>(mlp, W2, 128, b2, h1, ln2h_g, ln2h_b, out_h, 128, NN);
    // out_e = LN1e(conn + ce @ Eo_w + Eo_b)
    tgemm<128, 2><<<dim3(gE, 1), 256>>>(ce, Eo_w, 128, Eo_b, conn, ln1e_g, ln1e_b, out_e, 128, EE);
}

// round 9
// speedup vs baseline: 1.4060x; 1.0091x over previous
#include <cuda_runtime.h>
#include <cstdint>

#define NN 50000
#define EE 600000
#define HIDD 128
#define NH 8
#define DDIM 16

// ---------------- scratch (device globals; no allocation allowed) ----------------
__device__ float g_Qh[(size_t)NN * HIDD];
__device__ float g_Kh[(size_t)NN * HIDD];
__device__ float g_Vh[(size_t)NN * HIDD];
__device__ float g_Eh[(size_t)EE * 256];   // [Ew | Eb] per edge
__device__ float g_ce[(size_t)EE * HIDD];  // conn_e / e_attn
__device__ float g_ssum[(size_t)NN * NH];
__device__ float g_agg[(size_t)NN * HIDD];
__device__ float g_row[(size_t)NN * HIDD];
__device__ float g_hpre[(size_t)NN * HIDD];
__device__ float g_h1[(size_t)NN * HIDD];
__device__ float g_mlp[(size_t)NN * 256];

__device__ __forceinline__ float to_tf32(float x) {
    float r;
    asm("cvt.rna.tf32.f32 %0, %1;" : "=f"(r) : "f"(x));
    return r;
}

__device__ __forceinline__ void mma8(float* c, const uint32_t* a, const uint32_t* b) {
    asm volatile(
        "mma.sync.aligned.m16n8k8.row.col.f32.tf32.tf32.f32 "
        "{%0,%1,%2,%3},{%4,%5,%6,%7},{%8,%9},{%0,%1,%2,%3};"
        : "+f"(c[0]), "+f"(c[1]), "+f"(c[2]), "+f"(c[3])
        : "r"(a[0]), "r"(a[1]), "r"(a[2]), "r"(a[3]), "r"(b[0]), "r"(b[1]));
}

// ---------------- TF32 tensor-core GEMM: 256 thr, 8 warps in 4m x 2n grid -------
// Warp tile 32m x 64n, block tile 128x128.
// 2-stage smem double buffer + register prefetch: ONE barrier per k-chunk;
// mma(stage) overlaps LDG(kt+1), STS targets stage^1 (consumer a full chunk away).
// EPI 0: C = acc (+bias)          EPI 1: C = relu(acc + bias)
// EPI 2: C = LN(resid + acc + bias)*g + b  (grid.y==1, ldc==128; cross-warp row
//        reduction through smem since a row spans the 2 n-warps)
#define SMS 136
template <int KD, int EPI>
__global__ void __launch_bounds__(256, 2) tgemm(
    const float* __restrict__ A, const float* __restrict__ W, int ldw,
    const float* __restrict__ bias, const float* __restrict__ resid,
    const float* __restrict__ lng, const float* __restrict__ lnb,
    float* __restrict__ C, int ldc, int M)
{
    __shared__ float As[2][16][SMS];
    __shared__ float Ws[2][16][SMS];
    __shared__ float part[128][2][2];   // [row][wn][{sum, sumsq}] for EPI 2

    const int t = threadIdx.x;
    const int lane = t & 31;
    const int wid = t >> 5;            // 0..7
    const int wn = wid & 1;            // n half (64 cols)
    const int wm = wid >> 1;           // m quarter (32 rows)
    const int m0b = blockIdx.x * 128;
    const int n0 = blockIdx.y * 128;
    const int wm0 = wm * 32;
    const int wn0 = wn * 64;
    const int gr = lane >> 2;
    const int kq = lane & 3;

    float acc[2][8][4];
#pragma unroll
    for (int s = 0; s < 2; s++)
#pragma unroll
        for (int i = 0; i < 8; i++) { acc[s][i][0] = acc[s][i][1] = acc[s][i][2] = acc[s][i][3] = 0.f; }

    const int arow = t >> 2;           // 0..63
    const int acol = (t & 3) * 4;      // 0,4,8,12
    const int wrow = t >> 5;           // 0..7
    const int wcol = (t & 31) * 4;     // 0..124

    float4 aR[2], wR[2];

    // prologue: load + store k-chunk 0 into stage 0
#pragma unroll
    for (int p = 0; p < 2; p++) {
        int row = m0b + arow + p * 64;
        aR[p] = make_float4(0.f, 0.f, 0.f, 0.f);
        if (row < M) aR[p] = *(const float4*)&A[(size_t)row * KD + acol];
        int kr = wrow + p * 8;
        wR[p] = *(const float4*)&W[(size_t)kr * ldw + n0 + wcol];
    }
#pragma unroll
    for (int p = 0; p < 2; p++) {
        int r = arow + p * 64;
        As[0][acol + 0][r] = to_tf32(aR[p].x); As[0][acol + 1][r] = to_tf32(aR[p].y);
        As[0][acol + 2][r] = to_tf32(aR[p].z); As[0][acol + 3][r] = to_tf32(aR[p].w);
        int kr = wrow + p * 8;
        Ws[0][kr][wcol + 0] = to_tf32(wR[p].x); Ws[0][kr][wcol + 1] = to_tf32(wR[p].y);
        Ws[0][kr][wcol + 2] = to_tf32(wR[p].z); Ws[0][kr][wcol + 3] = to_tf32(wR[p].w);
    }

    int stage = 0;
    for (int kt = 0; kt < KD; kt += 16) {
        const bool has_next = (kt + 16 < KD);
        // issue next chunk's global loads first (in flight during mma)
        if (has_next) {
#pragma unroll
            for (int p = 0; p < 2; p++) {
                int row = m0b + arow + p * 64;
                aR[p] = make_float4(0.f, 0.f, 0.f, 0.f);
                if (row < M) aR[p] = *(const float4*)&A[(size_t)row * KD + kt + 16 + acol];
                int kr = wrow + p * 8;
                wR[p] = *(const float4*)&W[(size_t)(kt + 16 + kr) * ldw + n0 + wcol];
            }
        }
        __syncthreads();   // stage's STS visible; stage^1 reads (mma kt-1) all done
#pragma unroll
        for (int ks = 0; ks < 16; ks += 8) {
            uint32_t a[2][4];
#pragma unroll
            for (int s = 0; s < 2; s++) {
                int mb = wm0 + s * 16;
                a[s][0] = __float_as_uint(As[stage][ks + kq][mb + gr]);
                a[s][1] = __float_as_uint(As[stage][ks + kq][mb + 8 + gr]);
                a[s][2] = __float_as_uint(As[stage][ks + 4 + kq][mb + gr]);
                a[s][3] = __float_as_uint(As[stage][ks + 4 + kq][mb + 8 + gr]);
            }
#pragma unroll
            for (int nf = 0; nf < 8; nf++) {
                uint32_t b[2];
                b[0] = __float_as_uint(Ws[stage][ks + kq][wn0 + nf * 8 + gr]);
                b[1] = __float_as_uint(Ws[stage][ks + 4 + kq][wn0 + nf * 8 + gr]);
                mma8(acc[0][nf], a[0], b);
                mma8(acc[1][nf], a[1], b);
            }
        }
        if (has_next) {
            int nst = stage ^ 1;
#pragma unroll
            for (int p = 0; p < 2; p++) {
                int r = arow + p * 64;
                As[nst][acol + 0][r] = to_tf32(aR[p].x); As[nst][acol + 1][r] = to_tf32(aR[p].y);
                As[nst][acol + 2][r] = to_tf32(aR[p].z); As[nst][acol + 3][r] = to_tf32(aR[p].w);
                int kr = wrow + p * 8;
                Ws[nst][kr][wcol + 0] = to_tf32(wR[p].x); Ws[nst][kr][wcol + 1] = to_tf32(wR[p].y);
                Ws[nst][kr][wcol + 2] = to_tf32(wR[p].z); Ws[nst][kr][wcol + 3] = to_tf32(wR[p].w);
            }
        }
        stage ^= 1;
    }

    if (EPI == 0 || EPI == 1) {
#pragma unroll
        for (int s = 0; s < 2; s++)
#pragma unroll
        for (int half = 0; half < 2; half++) {
            int r = m0b + wm0 + s * 16 + gr + half * 8;
            if (r >= M) continue;
#pragma unroll
            for (int nf = 0; nf < 8; nf++) {
                int c = n0 + wn0 + nf * 8 + 2 * kq;
                float v0 = acc[s][nf][half * 2 + 0];
                float v1 = acc[s][nf][half * 2 + 1];
                if (bias) { v0 += bias[c]; v1 += bias[c + 1]; }
                if (EPI == 1) { v0 = fmaxf(v0, 0.f); v1 = fmaxf(v1, 0.f); }
                *(float2*)&C[(size_t)r * ldc + c] = make_float2(v0, v1);
            }
        }
    } else {
        // EPI 2: LayerNorm with cross-warp (2 n-halves) row reduction via smem.
        float v[2][2][16];   // [s][half][16 cols owned in this n-half]
#pragma unroll
        for (int s = 0; s < 2; s++)
#pragma unroll
        for (int half = 0; half < 2; half++) {
            int r = m0b + wm0 + s * 16 + gr + half * 8;
            bool ok = (r < M);
            float sm = 0.f, s2 = 0.f;
#pragma unroll
            for (int nf = 0; nf < 8; nf++) {
                int c = wn0 + nf * 8 + 2 * kq;
                float x0 = acc[s][nf][half * 2 + 0] + bias[c];
                float x1 = acc[s][nf][half * 2 + 1] + bias[c + 1];
                if (ok) {
                    float2 rr = *(const float2*)&resid[(size_t)r * 128 + c];
                    x0 += rr.x; x1 += rr.y;
                }
                v[s][half][2 * nf] = x0; v[s][half][2 * nf + 1] = x1;
                sm += x0 + x1;
                s2 += x0 * x0 + x1 * x1;
            }
#pragma unroll
            for (int off = 1; off < 4; off <<= 1) {
                sm += __shfl_xor_sync(0xffffffffu, sm, off);
                s2 += __shfl_xor_sync(0xffffffffu, s2, off);
            }
            if (kq == 0) {
                int lr = wm0 + s * 16 + gr + half * 8;
                part[lr][wn][0] = sm;
                part[lr][wn][1] = s2;
            }
        }
        __syncthreads();
#pragma unroll
        for (int s = 0; s < 2; s++)
#pragma unroll
        for (int half = 0; half < 2; half++) {
            int lr = wm0 + s * 16 + gr + half * 8;
            int r = m0b + lr;
            if (r >= M) continue;
            float sm = part[lr][0][0] + part[lr][1][0];
            float s2 = part[lr][0][1] + part[lr][1][1];
            float mean = sm * (1.f / 128.f);
            float var = s2 * (1.f / 128.f) - mean * mean;
            float rstd = rsqrtf(var + 1e-5f);
#pragma unroll
            for (int nf = 0; nf < 8; nf++) {
                int c = wn0 + nf * 8 + 2 * kq;
                float o0 = (v[s][half][2 * nf] - mean) * rstd * lng[c] + lnb[c];
                float o1 = (v[s][half][2 * nf + 1] - mean) * rstd * lng[c + 1] + lnb[c + 1];
                *(float2*)&C[(size_t)r * 128 + c] = make_float2(o0, o1);
            }
        }
    }
}

// ---------------- edge pass: conn_e, scores, segment accumulation ----------------
// one warp per edge. Softmax max-shift dropped (scores clipped to +-5 -> exact).
__global__ void __launch_bounds__(256) edge_kernel(const int* __restrict__ ei,
                                                   const float* __restrict__ Aw)
{
    int e = (int)((blockIdx.x * (size_t)blockDim.x + threadIdx.x) >> 5);
    int l = threadIdx.x & 31;
    if (e >= EE) return;
    int dst = ei[e];
    int src = ei[EE + e];
    int c0 = l * 4;
    int h = l >> 2;
    int dbase = (l & 3) * 4;

    float4 q = *(const float4*)&g_Qh[(size_t)dst * HIDD + c0];
    float4 kk = *(const float4*)&g_Kh[(size_t)src * HIDD + c0];
    float4 ew = *(const float4*)&g_Eh[(size_t)e * 256 + c0];
    float4 eb = *(const float4*)&g_Eh[(size_t)e * 256 + 128 + c0];
    float4 vv = *(const float4*)&g_Vh[(size_t)src * HIDD + c0];

    const float* qf = (const float*)&q;
    const float* kf = (const float*)&kk;
    const float* ewf = (const float*)&ew;
    const float* ebf = (const float*)&eb;
    const float* vf = (const float*)&vv;

    float ce[4];
    float part = 0.f;
#pragma unroll
    for (int i = 0; i < 4; i++) {
        float m = qf[i] + kf[i];
        float cc = m * ewf[i];
        float ss = sqrtf(fabsf(cc));
        ss = (cc >= 0.f) ? ss : -ss;          // signed sqrt
        float val = ss + ebf[i];
        ce[i] = fmaxf(val, 0.f);
        part += ce[i] * Aw[(dbase + i) * NH + h];
    }
    *(float4*)&g_ce[(size_t)e * HIDD + c0] = make_float4(ce[0], ce[1], ce[2], ce[3]);

    part += __shfl_xor_sync(0xffffffffu, part, 1);
    part += __shfl_xor_sync(0xffffffffu, part, 2);
    float s = fminf(fmaxf(part, -5.f), 5.f);
    float p = __expf(s);

    if ((l & 3) == 0) atomicAdd(&g_ssum[(size_t)dst * NH + h], p);
    float4 av = make_float4(vf[0] * p, vf[1] * p, vf[2] * p, vf[3] * p);
    float4 rv = make_float4(ce[0] * p, ce[1] * p, ce[2] * p, ce[3] * p);
    atomicAdd((float4*)&g_agg[(size_t)dst * HIDD + c0], av);
    atomicAdd((float4*)&g_row[(size_t)dst * HIDD + c0], rv);
}

// ---------------- node pass: normalize, rowV = row @ Bw, deg scaling ----------------
__global__ void __launch_bounds__(256) node_kernel(const float* __restrict__ Bw,
                                                   const float* __restrict__ deg_coef,
                                                   const float* __restrict__ log_deg)
{
    __shared__ float rbuf[8][HIDD];
    int n = (int)((blockIdx.x * (size_t)blockDim.x + threadIdx.x) >> 5);
    int wl = (threadIdx.x >> 5) & 7;
    int l = threadIdx.x & 31;
    if (n >= NN) return;
    int h = l >> 2;
    int c0 = l * 4;

    float rs = 1.f / (g_ssum[(size_t)n * NH + h] + 1e-16f);
    float4 a = *(const float4*)&g_agg[(size_t)n * HIDD + c0];
    float4 r = *(const float4*)&g_row[(size_t)n * HIDD + c0];
    a.x *= rs; a.y *= rs; a.z *= rs; a.w *= rs;
    r.x *= rs; r.y *= rs; r.z *= rs; r.w *= rs;
    *(float4*)&rbuf[wl][c0] = r;
    __syncwarp();

    float4 q = *(const float4*)&g_Qh[(size_t)n * HIDD + c0];
    const float* af = (const float*)&a;
    const float* qf = (const float*)&q;
    float ld = log_deg[n];

    float out[4];
#pragma unroll
    for (int i = 0; i < 4; i++) {
        int c = c0 + i;
        float rv = 0.f;
#pragma unroll
        for (int d = 0; d < DDIM; d++)
            rv = fmaf(rbuf[wl][h * DDIM + d], __ldg(&Bw[d * HIDD + c]), rv);
        float ha = qf[i] + af[i] + rv;
        out[i] = ha * (deg_coef[2 * c] + ld * deg_coef[2 * c + 1]);
    }
    *(float4*)&g_hpre[(size_t)n * HIDD + c0] = make_float4(out[0], out[1], out[2], out[3]);
}

// ---------------- launch ----------------
extern "C" void kernel_launch(void* const* d_in, const int* in_sizes, int n_in,
                              void* d_out, int out_size)
{
    const float* x        = (const float*)d_in[0];
    const float* conn     = (const float*)d_in[1];
    const float* log_deg  = (const float*)d_in[2];
    const int*   ei       = (const int*)d_in[3];
    const float* WQ       = (const float*)d_in[4];
    const float* WK       = (const float*)d_in[5];
    const float* WV       = (const float*)d_in[6];
    const float* WE       = (const float*)d_in[7];
    const float* Aw       = (const float*)d_in[8];
    const float* Bw       = (const float*)d_in[9];
    const float* Ho_w     = (const float*)d_in[10];
    const float* Ho_b     = (const float*)d_in[11];
    const float* Eo_w     = (const float*)d_in[12];
    const float* Eo_b     = (const float*)d_in[13];
    const float* deg_coef = (const float*)d_in[14];
    const float* ln1h_g   = (const float*)d_in[15];
    const float* ln1h_b   = (const float*)d_in[16];
    const float* ln1e_g   = (const float*)d_in[17];
    const float* ln1e_b   = (const float*)d_in[18];
    const float* ln2h_g   = (const float*)d_in[19];
    const float* ln2h_b   = (const float*)d_in[20];
    const float* W1       = (const float*)d_in[21];
    const float* b1       = (const float*)d_in[22];
    const float* W2       = (const float*)d_in[23];
    const float* b2       = (const float*)d_in[24];

    float* out_h = (float*)d_out;
    float* out_e = out_h + (size_t)NN * HIDD;

    float *Qh, *Kh, *Vh, *Eh, *ce, *ssum, *agg, *row, *hpre, *h1, *mlp;
    cudaGetSymbolAddress((void**)&Qh, g_Qh);
    cudaGetSymbolAddress((void**)&Kh, g_Kh);
    cudaGetSymbolAddress((void**)&Vh, g_Vh);
    cudaGetSymbolAddress((void**)&Eh, g_Eh);
    cudaGetSymbolAddress((void**)&ce, g_ce);
    cudaGetSymbolAddress((void**)&ssum, g_ssum);
    cudaGetSymbolAddress((void**)&agg, g_agg);
    cudaGetSymbolAddress((void**)&row, g_row);
    cudaGetSymbolAddress((void**)&hpre, g_hpre);
    cudaGetSymbolAddress((void**)&h1, g_h1);
    cudaGetSymbolAddress((void**)&mlp, g_mlp);

    const int gN = (NN + 127) / 128;   // 391
    const int gE = (EE + 127) / 128;   // 4688

    cudaMemsetAsync(ssum, 0, (size_t)NN * NH * sizeof(float), 0);
    cudaMemsetAsync(agg, 0, (size_t)NN * HIDD * sizeof(float), 0);
    cudaMemsetAsync(row, 0, (size_t)NN * HIDD * sizeof(float), 0);

    // Qh, Kh, Vh
    tgemm<128, 0><<<dim3(gN, 1), 256>>>(x, WQ, 128, nullptr, nullptr, nullptr, nullptr, Qh, 128, NN);
    tgemm<128, 0><<<dim3(gN, 1), 256>>>(x, WK, 128, nullptr, nullptr, nullptr, nullptr, Kh, 128, NN);
    tgemm<128, 0><<<dim3(gN, 1), 256>>>(x, WV, 128, nullptr, nullptr, nullptr, nullptr, Vh, 128, NN);
    // Eh = conn @ WE  [E,256]
    tgemm<128, 0><<<dim3(gE, 2), 256>>>(conn, WE, 256, nullptr, nullptr, nullptr, nullptr, Eh, 256, EE);

    // edge pass (conn_e + softmax-weighted segment sums)
    edge_kernel<<<(EE * 32 + 255) / 256, 256>>>(ei, Aw);
    // node pass -> h_pre
    node_kernel<<<(NN * 32 + 255) / 256, 256>>>(Bw, deg_coef, log_deg);

    // h1 = LN1h(x + hpre @ Ho_w + Ho_b)
    tgemm<128, 2><<<dim3(gN, 1), 256>>>(hpre, Ho_w, 128, Ho_b, x, ln1h_g, ln1h_b, h1, 128, NN);
    // mlp = relu(h1 @ W1 + b1)
    tgemm<128, 1><<<dim3(gN, 2), 256>>>(h1, W1, 256, b1, nullptr, nullptr, nullptr, mlp, 256, NN);
    // out_h = LN2h(h1 + mlp @ W2 + b2)
    tgemm<256, 2><<<dim3(gN, 1), 256>>>(mlp, W2, 128, b2, h1, ln2h_g, ln2h_b, out_h, 128, NN);
    // out_e = LN1e(conn + ce @ Eo_w + Eo_b)
    tgemm<128, 2><<<dim3(gE, 1), 256>>>(ce, Eo_w, 128, Eo_b, conn, ln1e_g, ln1e_b, out_e, 128, EE);
}

// round 13
// speedup vs baseline: 1.6076x; 1.1433x over previous
#include <cuda_runtime.h>
#include <cuda_fp16.h>
#include <cstdint>

#define NN 50000
#define EE 600000
#define HIDD 128
#define NH 8
#define DDIM 16

// ---------------- scratch (device globals; no allocation allowed) ----------------
__device__ float g_Qh[(size_t)NN * HIDD];
__device__ float g_Kh[(size_t)NN * HIDD];
__device__ float g_Vh[(size_t)NN * HIDD];
__device__ float g_Eh[(size_t)EE * 256];   // [Ew | Eb] per edge
__device__ float g_ce[(size_t)EE * HIDD];  // conn_e / e_attn
__device__ float g_ssum[(size_t)NN * NH];
__device__ float g_agg[(size_t)NN * HIDD];
__device__ float g_row[(size_t)NN * HIDD];
__device__ float g_hpre[(size_t)NN * HIDD];
__device__ float g_h1[(size_t)NN * HIDD];
__device__ float g_mlp[(size_t)NN * 256];

__device__ __forceinline__ void mma16(float* c, const uint32_t* a, const uint32_t* b) {
    asm volatile(
        "mma.sync.aligned.m16n8k16.row.col.f32.f16.f16.f32 "
        "{%0,%1,%2,%3},{%4,%5,%6,%7},{%8,%9},{%0,%1,%2,%3};"
        : "+f"(c[0]), "+f"(c[1]), "+f"(c[2]), "+f"(c[3])
        : "r"(a[0]), "r"(a[1]), "r"(a[2]), "r"(a[3]), "r"(b[0]), "r"(b[1]));
}

__device__ __forceinline__ uint32_t pack_h2(float lo, float hi) {
    __half2 h = __floats2half2_rn(lo, hi);   // lo -> low half
    return *(uint32_t*)&h;
}

// ---------------- FP16 tensor-core GEMM: 256 thr, 8 warps in 4m x 2n grid -------
// Warp tile 32m x 64n, block tile 128x128, fp16 inputs (11-bit significand, same
// as tf32), fp32 accumulate. Smem stores packed half2 along k: As2[k2][m],
// Ws2[k2][n] (stride 136 -> fragment LDS conflict-free). Half the smem bytes and
// half the mma instructions vs tf32 m16n8k8.
// 2-stage smem double buffer + register prefetch: ONE barrier per k-chunk.
// EPI 0: C = acc (+bias)          EPI 1: C = relu(acc + bias)
// EPI 2: C = LN(resid + acc + bias)*g + b  (grid.y==1, ldc==128; cross-warp row
//        reduction through smem since a row spans the 2 n-warps)
#define SMS 136
template <int KD, int EPI>
__global__ void __launch_bounds__(256, 2) tgemm(
    const float* __restrict__ A, const float* __restrict__ W, int ldw,
    const float* __restrict__ bias, const float* __restrict__ resid,
    const float* __restrict__ lng, const float* __restrict__ lnb,
    float* __restrict__ C, int ldc, int M)
{
    __shared__ uint32_t As2[2][8][SMS];   // [stage][k2][m] packed half2 (k, k+1)
    __shared__ uint32_t Ws2[2][8][SMS];   // [stage][k2][n]
    __shared__ float part[128][2][2];     // [row][wn][{sum, sumsq}] for EPI 2

    const int t = threadIdx.x;
    const int lane = t & 31;
    const int wid = t >> 5;            // 0..7
    const int wn = wid & 1;            // n half (64 cols)
    const int wm = wid >> 1;           // m quarter (32 rows)
    const int m0b = blockIdx.x * 128;
    const int n0 = blockIdx.y * 128;
    const int wm0 = wm * 32;
    const int wn0 = wn * 64;
    const int gr = lane >> 2;
    const int kq = lane & 3;

    float acc[2][8][4];
#pragma unroll
    for (int s = 0; s < 2; s++)
#pragma unroll
        for (int i = 0; i < 8; i++) { acc[s][i][0] = acc[s][i][1] = acc[s][i][2] = acc[s][i][3] = 0.f; }

    const int arow = t >> 2;           // 0..63
    const int acol = (t & 3) * 4;      // 0,4,8,12  (k offset of the float4)
    const int ak2 = acol >> 1;         // half2 row: acol/2, acol/2+1
    const int wj = t >> 5;             // 0..7 : k-row pair (2j, 2j+1)
    const int wcol = (t & 31) * 4;     // 0..124

    float4 aR[2], wRa, wRb;

    // prologue: load + convert + store k-chunk 0 into stage 0
#pragma unroll
    for (int p = 0; p < 2; p++) {
        int row = m0b + arow + p * 64;
        aR[p] = make_float4(0.f, 0.f, 0.f, 0.f);
        if (row < M) aR[p] = *(const float4*)&A[(size_t)row * KD + acol];
    }
    wRa = *(const float4*)&W[(size_t)(2 * wj) * ldw + n0 + wcol];
    wRb = *(const float4*)&W[(size_t)(2 * wj + 1) * ldw + n0 + wcol];
#pragma unroll
    for (int p = 0; p < 2; p++) {
        int m = arow + p * 64;
        As2[0][ak2 + 0][m] = pack_h2(aR[p].x, aR[p].y);
        As2[0][ak2 + 1][m] = pack_h2(aR[p].z, aR[p].w);
    }
    {
        uint4 wv;
        wv.x = pack_h2(wRa.x, wRb.x); wv.y = pack_h2(wRa.y, wRb.y);
        wv.z = pack_h2(wRa.z, wRb.z); wv.w = pack_h2(wRa.w, wRb.w);
        *(uint4*)&Ws2[0][wj][wcol] = wv;
    }

    int stage = 0;
    for (int kt = 0; kt < KD; kt += 16) {
        const bool has_next = (kt + 16 < KD);
        // issue next chunk's global loads first (in flight during mma)
        if (has_next) {
#pragma unroll
            for (int p = 0; p < 2; p++) {
                int row = m0b + arow + p * 64;
                aR[p] = make_float4(0.f, 0.f, 0.f, 0.f);
                if (row < M) aR[p] = *(const float4*)&A[(size_t)row * KD + kt + 16 + acol];
            }
            wRa = *(const float4*)&W[(size_t)(kt + 16 + 2 * wj) * ldw + n0 + wcol];
            wRb = *(const float4*)&W[(size_t)(kt + 16 + 2 * wj + 1) * ldw + n0 + wcol];
        }
        __syncthreads();   // stage's STS visible; stage^1 reads (mma kt-1) all done
        {
            uint32_t a[2][4];
#pragma unroll
            for (int s = 0; s < 2; s++) {
                int mb = wm0 + s * 16;
                a[s][0] = As2[stage][kq][mb + gr];
                a[s][1] = As2[stage][kq][mb + 8 + gr];
                a[s][2] = As2[stage][kq + 4][mb + gr];
                a[s][3] = As2[stage][kq + 4][mb + 8 + gr];
            }
#pragma unroll
            for (int nf = 0; nf < 8; nf++) {
                uint32_t b[2];
                b[0] = Ws2[stage][kq][wn0 + nf * 8 + gr];
                b[1] = Ws2[stage][kq + 4][wn0 + nf * 8 + gr];
                mma16(acc[0][nf], a[0], b);
                mma16(acc[1][nf], a[1], b);
            }
        }
        if (has_next) {
            int nst = stage ^ 1;
#pragma unroll
            for (int p = 0; p < 2; p++) {
                int m = arow + p * 64;
                As2[nst][ak2 + 0][m] = pack_h2(aR[p].x, aR[p].y);
                As2[nst][ak2 + 1][m] = pack_h2(aR[p].z, aR[p].w);
            }
            uint4 wv;
            wv.x = pack_h2(wRa.x, wRb.x); wv.y = pack_h2(wRa.y, wRb.y);
            wv.z = pack_h2(wRa.z, wRb.z); wv.w = pack_h2(wRa.w, wRb.w);
            *(uint4*)&Ws2[nst][wj][wcol] = wv;
        }
        stage ^= 1;
    }

    if (EPI == 0 || EPI == 1) {
#pragma unroll
        for (int s = 0; s < 2; s++)
#pragma unroll
        for (int half = 0; half < 2; half++) {
            int r = m0b + wm0 + s * 16 + gr + half * 8;
            if (r >= M) continue;
#pragma unroll
            for (int nf = 0; nf < 8; nf++) {
                int c = n0 + wn0 + nf * 8 + 2 * kq;
                float v0 = acc[s][nf][half * 2 + 0];
                float v1 = acc[s][nf][half * 2 + 1];
                if (bias) { v0 += bias[c]; v1 += bias[c + 1]; }
                if (EPI == 1) { v0 = fmaxf(v0, 0.f); v1 = fmaxf(v1, 0.f); }
                *(float2*)&C[(size_t)r * ldc + c] = make_float2(v0, v1);
            }
        }
    } else {
        // EPI 2: LayerNorm with cross-warp (2 n-halves) row reduction via smem.
        float v[2][2][16];   // [s][half][16 cols owned in this n-half]
#pragma unroll
        for (int s = 0; s < 2; s++)
#pragma unroll
        for (int half = 0; half < 2; half++) {
            int r = m0b + wm0 + s * 16 + gr + half * 8;
            bool ok = (r < M);
            float sm = 0.f, s2 = 0.f;
#pragma unroll
            for (int nf = 0; nf < 8; nf++) {
                int c = wn0 + nf * 8 + 2 * kq;
                float x0 = acc[s][nf][half * 2 + 0] + bias[c];
                float x1 = acc[s][nf][half * 2 + 1] + bias[c + 1];
                if (ok) {
                    float2 rr = *(const float2*)&resid[(size_t)r * 128 + c];
                    x0 += rr.x; x1 += rr.y;
                }
                v[s][half][2 * nf] = x0; v[s][half][2 * nf + 1] = x1;
                sm += x0 + x1;
                s2 += x0 * x0 + x1 * x1;
            }
#pragma unroll
            for (int off = 1; off < 4; off <<= 1) {
                sm += __shfl_xor_sync(0xffffffffu, sm, off);
                s2 += __shfl_xor_sync(0xffffffffu, s2, off);
            }
            if (kq == 0) {
                int lr = wm0 + s * 16 + gr + half * 8;
                part[lr][wn][0] = sm;
                part[lr][wn][1] = s2;
            }
        }
        __syncthreads();
#pragma unroll
        for (int s = 0; s < 2; s++)
#pragma unroll
        for (int half = 0; half < 2; half++) {
            int lr = wm0 + s * 16 + gr + half * 8;
            int r = m0b + lr;
            if (r >= M) continue;
            float sm = part[lr][0][0] + part[lr][1][0];
            float s2 = part[lr][0][1] + part[lr][1][1];
            float mean = sm * (1.f / 128.f);
            float var = s2 * (1.f / 128.f) - mean * mean;
            float rstd = rsqrtf(var + 1e-5f);
#pragma unroll
            for (int nf = 0; nf < 8; nf++) {
                int c = wn0 + nf * 8 + 2 * kq;
                float o0 = (v[s][half][2 * nf] - mean) * rstd * lng[c] + lnb[c];
                float o1 = (v[s][half][2 * nf + 1] - mean) * rstd * lng[c + 1] + lnb[c + 1];
                *(float2*)&C[(size_t)r * 128 + c] = make_float2(o0, o1);
            }
        }
    }
}

// ---------------- edge pass: conn_e, scores, segment accumulation ----------------
// one warp per edge. Softmax max-shift dropped (scores clipped to +-5 -> exact).
__global__ void __launch_bounds__(256) edge_kernel(const int* __restrict__ ei,
                                                   const float* __restrict__ Aw)
{
    int e = (int)((blockIdx.x * (size_t)blockDim.x + threadIdx.x) >> 5);
    int l = threadIdx.x & 31;
    if (e >= EE) return;
    int dst = ei[e];
    int src = ei[EE + e];
    int c0 = l * 4;
    int h = l >> 2;
    int dbase = (l & 3) * 4;

    float4 q = *(const float4*)&g_Qh[(size_t)dst * HIDD + c0];
    float4 kk = *(const float4*)&g_Kh[(size_t)src * HIDD + c0];
    float4 ew = *(const float4*)&g_Eh[(size_t)e * 256 + c0];
    float4 eb = *(const float4*)&g_Eh[(size_t)e * 256 + 128 + c0];
    float4 vv = *(const float4*)&g_Vh[(size_t)src * HIDD + c0];

    const float* qf = (const float*)&q;
    const float* kf = (const float*)&kk;
    const float* ewf = (const float*)&ew;
    const float* ebf = (const float*)&eb;
    const float* vf = (const float*)&vv;

    float ce[4];
    float part = 0.f;
#pragma unroll
    for (int i = 0; i < 4; i++) {
        float m = qf[i] + kf[i];
        float cc = m * ewf[i];
        float ss = sqrtf(fabsf(cc));
        ss = (cc >= 0.f) ? ss : -ss;          // signed sqrt
        float val = ss + ebf[i];
        ce[i] = fmaxf(val, 0.f);
        part += ce[i] * Aw[(dbase + i) * NH + h];
    }
    *(float4*)&g_ce[(size_t)e * HIDD + c0] = make_float4(ce[0], ce[1], ce[2], ce[3]);

    part += __shfl_xor_sync(0xffffffffu, part, 1);
    part += __shfl_xor_sync(0xffffffffu, part, 2);
    float s = fminf(fmaxf(part, -5.f), 5.f);
    float p = __expf(s);

    if ((l & 3) == 0) atomicAdd(&g_ssum[(size_t)dst * NH + h], p);
    float4 av = make_float4(vf[0] * p, vf[1] * p, vf[2] * p, vf[3] * p);
    float4 rv = make_float4(ce[0] * p, ce[1] * p, ce[2] * p, ce[3] * p);
    atomicAdd((float4*)&g_agg[(size_t)dst * HIDD + c0], av);
    atomicAdd((float4*)&g_row[(size_t)dst * HIDD + c0], rv);
}

// ---------------- node pass: normalize, rowV = row @ Bw, deg scaling ----------------
__global__ void __launch_bounds__(256) node_kernel(const float* __restrict__ Bw,
                                                   const float* __restrict__ deg_coef,
                                                   const float* __restrict__ log_deg)
{
    __shared__ float rbuf[8][HIDD];
    int n = (int)((blockIdx.x * (size_t)blockDim.x + threadIdx.x) >> 5);
    int wl = (threadIdx.x >> 5) & 7;
    int l = threadIdx.x & 31;
    if (n >= NN) return;
    int h = l >> 2;
    int c0 = l * 4;

    float rs = 1.f / (g_ssum[(size_t)n * NH + h] + 1e-16f);
    float4 a = *(const float4*)&g_agg[(size_t)n * HIDD + c0];
    float4 r = *(const float4*)&g_row[(size_t)n * HIDD + c0];
    a.x *= rs; a.y *= rs; a.z *= rs; a.w *= rs;
    r.x *= rs; r.y *= rs; r.z *= rs; r.w *= rs;
    *(float4*)&rbuf[wl][c0] = r;
    __syncwarp();

    float4 q = *(const float4*)&g_Qh[(size_t)n * HIDD + c0];
    const float* af = (const float*)&a;
    const float* qf = (const float*)&q;
    float ld = log_deg[n];

    float out[4];
#pragma unroll
    for (int i = 0; i < 4; i++) {
        int c = c0 + i;
        float rv = 0.f;
#pragma unroll
        for (int d = 0; d < DDIM; d++)
            rv = fmaf(rbuf[wl][h * DDIM + d], __ldg(&Bw[d * HIDD + c]), rv);
        float ha = qf[i] + af[i] + rv;
        out[i] = ha * (deg_coef[2 * c] + ld * deg_coef[2 * c + 1]);
    }
    *(float4*)&g_hpre[(size_t)n * HIDD + c0] = make_float4(out[0], out[1], out[2], out[3]);
}

// ---------------- launch ----------------
extern "C" void kernel_launch(void* const* d_in, const int* in_sizes, int n_in,
                              void* d_out, int out_size)
{
    const float* x        = (const float*)d_in[0];
    const float* conn     = (const float*)d_in[1];
    const float* log_deg  = (const float*)d_in[2];
    const int*   ei       = (const int*)d_in[3];
    const float* WQ       = (const float*)d_in[4];
    const float* WK       = (const float*)d_in[5];
    const float* WV       = (const float*)d_in[6];
    const float* WE       = (const float*)d_in[7];
    const float* Aw       = (const float*)d_in[8];
    const float* Bw       = (const float*)d_in[9];
    const float* Ho_w     = (const float*)d_in[10];
    const float* Ho_b     = (const float*)d_in[11];
    const float* Eo_w     = (const float*)d_in[12];
    const float* Eo_b     = (const float*)d_in[13];
    const float* deg_coef = (const float*)d_in[14];
    const float* ln1h_g   = (const float*)d_in[15];
    const float* ln1h_b   = (const float*)d_in[16];
    const float* ln1e_g   = (const float*)d_in[17];
    const float* ln1e_b   = (const float*)d_in[18];
    const float* ln2h_g   = (const float*)d_in[19];
    const float* ln2h_b   = (const float*)d_in[20];
    const float* W1       = (const float*)d_in[21];
    const float* b1       = (const float*)d_in[22];
    const float* W2       = (const float*)d_in[23];
    const float* b2       = (const float*)d_in[24];

    float* out_h = (float*)d_out;
    float* out_e = out_h + (size_t)NN * HIDD;

    float *Qh, *Kh, *Vh, *Eh, *ce, *ssum, *agg, *row, *hpre, *h1, *mlp;
    cudaGetSymbolAddress((void**)&Qh, g_Qh);
    cudaGetSymbolAddress((void**)&Kh, g_Kh);
    cudaGetSymbolAddress((void**)&Vh, g_Vh);
    cudaGetSymbolAddress((void**)&Eh, g_Eh);
    cudaGetSymbolAddress((void**)&ce, g_ce);
    cudaGetSymbolAddress((void**)&ssum, g_ssum);
    cudaGetSymbolAddress((void**)&agg, g_agg);
    cudaGetSymbolAddress((void**)&row, g_row);
    cudaGetSymbolAddress((void**)&hpre, g_hpre);
    cudaGetSymbolAddress((void**)&h1, g_h1);
    cudaGetSymbolAddress((void**)&mlp, g_mlp);

    const int gN = (NN + 127) / 128;   // 391
    const int gE = (EE + 127) / 128;   // 4688

    cudaMemsetAsync(ssum, 0, (size_t)NN * NH * sizeof(float), 0);
    cudaMemsetAsync(agg, 0, (size_t)NN * HIDD * sizeof(float), 0);
    cudaMemsetAsync(row, 0, (size_t)NN * HIDD * sizeof(float), 0);

    // Qh, Kh, Vh
    tgemm<128, 0><<<dim3(gN, 1), 256>>>(x, WQ, 128, nullptr, nullptr, nullptr, nullptr, Qh, 128, NN);
    tgemm<128, 0><<<dim3(gN, 1), 256>>>(x, WK, 128, nullptr, nullptr, nullptr, nullptr, Kh, 128, NN);
    tgemm<128, 0><<<dim3(gN, 1), 256>>>(x, WV, 128, nullptr, nullptr, nullptr, nullptr, Vh, 128, NN);
    // Eh = conn @ WE  [E,256]
    tgemm<128, 0><<<dim3(gE, 2), 256>>>(conn, WE, 256, nullptr, nullptr, nullptr, nullptr, Eh, 256, EE);

    // edge pass (conn_e + softmax-weighted segment sums)
    edge_kernel<<<(EE * 32 + 255) / 256, 256>>>(ei, Aw);
    // node pass -> h_pre
    node_kernel<<<(NN * 32 + 255) / 256, 256>>>(Bw, deg_coef, log_deg);

    // h1 = LN1h(x + hpre @ Ho_w + Ho_b)
    tgemm<128, 2><<<dim3(gN, 1), 256>>>(hpre, Ho_w, 128, Ho_b, x, ln1h_g, ln1h_b, h1, 128, NN);
    // mlp = relu(h1 @ W1 + b1)
    tgemm<128, 1><<<dim3(gN, 2), 256>>>(h1, W1, 256, b1, nullptr, nullptr, nullptr, mlp, 256, NN);
    // out_h = LN2h(h1 + mlp @ W2 + b2)
    tgemm<256, 2><<<dim3(gN, 1), 256>>>(mlp, W2, 128, b2, h1, ln2h_g, ln2h_b, out_h, 128, NN);
    // out_e = LN1e(conn + ce @ Eo_w + Eo_b)
    tgemm<128, 2><<<dim3(gE, 1), 256>>>(ce, Eo_w, 128, Eo_b, conn, ln1e_g, ln1e_b, out_e, 128, EE);
}

// round 14
// speedup vs baseline: 1.8085x; 1.1250x over previous
#include <cuda_runtime.h>
#include <cuda_fp16.h>
#include <cstdint>

#define NN 50000
#define EE 600000
#define HIDD 128
#define NH 8
#define DDIM 16

// ---------------- scratch (device globals; no allocation allowed) ----------------
__device__ float  g_Qh[(size_t)NN * HIDD];
__device__ float  g_Kh[(size_t)NN * HIDD];
__device__ float  g_Vh[(size_t)NN * HIDD];
__device__ __half g_Eh[(size_t)EE * 256];   // [Ew | Eb] per edge, fp16
__device__ __half g_ce[(size_t)EE * HIDD];  // conn_e / e_attn, fp16
__device__ float  g_ssum[(size_t)NN * NH];
__device__ float  g_agg[(size_t)NN * HIDD];
__device__ float  g_row[(size_t)NN * HIDD];
__device__ float  g_hpre[(size_t)NN * HIDD];
__device__ float  g_h1[(size_t)NN * HIDD];
__device__ float  g_mlp[(size_t)NN * 256];

__device__ __forceinline__ void mma16(float* c, const uint32_t* a, const uint32_t* b) {
    asm volatile(
        "mma.sync.aligned.m16n8k16.row.col.f32.f16.f16.f32 "
        "{%0,%1,%2,%3},{%4,%5,%6,%7},{%8,%9},{%0,%1,%2,%3};"
        : "+f"(c[0]), "+f"(c[1]), "+f"(c[2]), "+f"(c[3])
        : "r"(a[0]), "r"(a[1]), "r"(a[2]), "r"(a[3]), "r"(b[0]), "r"(b[1]));
}

__device__ __forceinline__ uint32_t pack_h2(float lo, float hi) {
    __half2 h = __floats2half2_rn(lo, hi);   // lo -> low half
    return *(uint32_t*)&h;
}

// ---------------- FP16 tensor-core GEMM: 256 thr, 8 warps in 4m x 2n grid -------
// Warp tile 32m x 64n, block tile 128x128, fp16 inputs, fp32 accumulate.
// AHALF: A is __half (packed half2 copied straight to smem, no cvt).
// CHALF: C written as __half (EPI 0 only).
// SWAPG: m-index from blockIdx.y, n-index from blockIdx.x (so the n-split CTAs
//        that share an A tile are launch-adjacent -> A re-read hits L2).
// 2-stage smem double buffer + register prefetch: ONE barrier per k-chunk.
// EPI 0: C = acc (+bias)          EPI 1: C = relu(acc + bias)
// EPI 2: C = LN(resid + acc + bias)*g + b  (single n-block, ldc==128)
#define SMS 136
template <int KD, int EPI, bool AHALF, bool CHALF, bool SWAPG>
__global__ void __launch_bounds__(256, 2) tgemm(
    const void* __restrict__ Av, const float* __restrict__ W, int ldw,
    const float* __restrict__ bias, const float* __restrict__ resid,
    const float* __restrict__ lng, const float* __restrict__ lnb,
    void* __restrict__ Cv, int ldc, int M)
{
    const float*  Af = (const float*)Av;
    const __half* Ah = (const __half*)Av;
    float*  Cf = (float*)Cv;
    __half* Ch = (__half*)Cv;

    __shared__ uint32_t As2[2][8][SMS];   // [stage][k2][m] packed half2 (k, k+1)
    __shared__ uint32_t Ws2[2][8][SMS];   // [stage][k2][n]
    __shared__ float part[128][2][2];     // [row][wn][{sum, sumsq}] for EPI 2

    const int t = threadIdx.x;
    const int lane = t & 31;
    const int wid = t >> 5;            // 0..7
    const int wn = wid & 1;            // n half (64 cols)
    const int wm = wid >> 1;           // m quarter (32 rows)
    const int bxm = SWAPG ? blockIdx.y : blockIdx.x;
    const int bxn = SWAPG ? blockIdx.x : blockIdx.y;
    const int m0b = bxm * 128;
    const int n0 = bxn * 128;
    const int wm0 = wm * 32;
    const int wn0 = wn * 64;
    const int gr = lane >> 2;
    const int kq = lane & 3;

    float acc[2][8][4];
#pragma unroll
    for (int s = 0; s < 2; s++)
#pragma unroll
        for (int i = 0; i < 8; i++) { acc[s][i][0] = acc[s][i][1] = acc[s][i][2] = acc[s][i][3] = 0.f; }

    const int arow = t >> 2;           // 0..63
    const int acol = (t & 3) * 4;      // 0,4,8,12  (k offset of the float4)
    const int ak2 = acol >> 1;         // half2 row: acol/2, acol/2+1
    const int wj = t >> 5;             // 0..7 : k-row pair (2j, 2j+1)
    const int wcol = (t & 31) * 4;     // 0..124

    float4 aRf[2]; uint2 aRh[2];
    float4 wRa, wRb;

    auto loadA = [&](int ko) {
#pragma unroll
        for (int p = 0; p < 2; p++) {
            int row = m0b + arow + p * 64;
            if (AHALF) {
                aRh[p] = make_uint2(0u, 0u);
                if (row < M) aRh[p] = *(const uint2*)&Ah[(size_t)row * KD + ko + acol];
            } else {
                aRf[p] = make_float4(0.f, 0.f, 0.f, 0.f);
                if (row < M) aRf[p] = *(const float4*)&Af[(size_t)row * KD + ko + acol];
            }
        }
    };
    auto loadW = [&](int ko) {
        wRa = *(const float4*)&W[(size_t)(ko + 2 * wj) * ldw + n0 + wcol];
        wRb = *(const float4*)&W[(size_t)(ko + 2 * wj + 1) * ldw + n0 + wcol];
    };
    auto stsAW = [&](int st) {
#pragma unroll
        for (int p = 0; p < 2; p++) {
            int m = arow + p * 64;
            if (AHALF) {
                As2[st][ak2 + 0][m] = aRh[p].x;
                As2[st][ak2 + 1][m] = aRh[p].y;
            } else {
                As2[st][ak2 + 0][m] = pack_h2(aRf[p].x, aRf[p].y);
                As2[st][ak2 + 1][m] = pack_h2(aRf[p].z, aRf[p].w);
            }
        }
        uint4 wv;
        wv.x = pack_h2(wRa.x, wRb.x); wv.y = pack_h2(wRa.y, wRb.y);
        wv.z = pack_h2(wRa.z, wRb.z); wv.w = pack_h2(wRa.w, wRb.w);
        *(uint4*)&Ws2[st][wj][wcol] = wv;
    };

    loadA(0); loadW(0); stsAW(0);

    int stage = 0;
    for (int kt = 0; kt < KD; kt += 16) {
        const bool has_next = (kt + 16 < KD);
        if (has_next) { loadA(kt + 16); loadW(kt + 16); }
        __syncthreads();   // stage's STS visible; stage^1 reads (mma kt-1) all done
        {
            uint32_t a[2][4];
#pragma unroll
            for (int s = 0; s < 2; s++) {
                int mb = wm0 + s * 16;
                a[s][0] = As2[stage][kq][mb + gr];
                a[s][1] = As2[stage][kq][mb + 8 + gr];
                a[s][2] = As2[stage][kq + 4][mb + gr];
                a[s][3] = As2[stage][kq + 4][mb + 8 + gr];
            }
#pragma unroll
            for (int nf = 0; nf < 8; nf++) {
                uint32_t b[2];
                b[0] = Ws2[stage][kq][wn0 + nf * 8 + gr];
                b[1] = Ws2[stage][kq + 4][wn0 + nf * 8 + gr];
                mma16(acc[0][nf], a[0], b);
                mma16(acc[1][nf], a[1], b);
            }
        }
        if (has_next) stsAW(stage ^ 1);
        stage ^= 1;
    }

    if (EPI == 0 || EPI == 1) {
#pragma unroll
        for (int s = 0; s < 2; s++)
#pragma unroll
        for (int half = 0; half < 2; half++) {
            int r = m0b + wm0 + s * 16 + gr + half * 8;
            if (r >= M) continue;
#pragma unroll
            for (int nf = 0; nf < 8; nf++) {
                int c = n0 + wn0 + nf * 8 + 2 * kq;
                float v0 = acc[s][nf][half * 2 + 0];
                float v1 = acc[s][nf][half * 2 + 1];
                if (bias) { v0 += bias[c]; v1 += bias[c + 1]; }
                if (EPI == 1) { v0 = fmaxf(v0, 0.f); v1 = fmaxf(v1, 0.f); }
                if (CHALF) {
                    *(uint32_t*)&Ch[(size_t)r * ldc + c] = pack_h2(v0, v1);
                } else {
                    *(float2*)&Cf[(size_t)r * ldc + c] = make_float2(v0, v1);
                }
            }
        }
    } else {
        // EPI 2: LayerNorm with cross-warp (2 n-halves) row reduction via smem.
        float v[2][2][16];   // [s][half][16 cols owned in this n-half]
#pragma unroll
        for (int s = 0; s < 2; s++)
#pragma unroll
        for (int half = 0; half < 2; half++) {
            int r = m0b + wm0 + s * 16 + gr + half * 8;
            bool ok = (r < M);
            float sm = 0.f, s2 = 0.f;
#pragma unroll
            for (int nf = 0; nf < 8; nf++) {
                int c = wn0 + nf * 8 + 2 * kq;
                float x0 = acc[s][nf][half * 2 + 0] + bias[c];
                float x1 = acc[s][nf][half * 2 + 1] + bias[c + 1];
                if (ok) {
                    float2 rr = *(const float2*)&resid[(size_t)r * 128 + c];
                    x0 += rr.x; x1 += rr.y;
                }
                v[s][half][2 * nf] = x0; v[s][half][2 * nf + 1] = x1;
                sm += x0 + x1;
                s2 += x0 * x0 + x1 * x1;
            }
#pragma unroll
            for (int off = 1; off < 4; off <<= 1) {
                sm += __shfl_xor_sync(0xffffffffu, sm, off);
                s2 += __shfl_xor_sync(0xffffffffu, s2, off);
            }
            if (kq == 0) {
                int lr = wm0 + s * 16 + gr + half * 8;
                part[lr][wn][0] = sm;
                part[lr][wn][1] = s2;
            }
        }
        __syncthreads();
#pragma unroll
        for (int s = 0; s < 2; s++)
#pragma unroll
        for (int half = 0; half < 2; half++) {
            int lr = wm0 + s * 16 + gr + half * 8;
            int r = m0b + lr;
            if (r >= M) continue;
            float sm = part[lr][0][0] + part[lr][1][0];
            float s2 = part[lr][0][1] + part[lr][1][1];
            float mean = sm * (1.f / 128.f);
            float var = s2 * (1.f / 128.f) - mean * mean;
            float rstd = rsqrtf(var + 1e-5f);
#pragma unroll
            for (int nf = 0; nf < 8; nf++) {
                int c = wn0 + nf * 8 + 2 * kq;
                float o0 = (v[s][half][2 * nf] - mean) * rstd * lng[c] + lnb[c];
                float o1 = (v[s][half][2 * nf + 1] - mean) * rstd * lng[c + 1] + lnb[c + 1];
                *(float2*)&Cf[(size_t)r * 128 + c] = make_float2(o0, o1);
            }
        }
    }
}

// ---------------- edge pass: conn_e, scores, segment accumulation ----------------
// one warp per edge. Softmax max-shift dropped (scores clipped to +-5 -> exact).
__global__ void __launch_bounds__(256) edge_kernel(const int* __restrict__ ei,
                                                   const float* __restrict__ Aw)
{
    int e = (int)((blockIdx.x * (size_t)blockDim.x + threadIdx.x) >> 5);
    int l = threadIdx.x & 31;
    if (e >= EE) return;
    int dst = ei[e];
    int src = ei[EE + e];
    int c0 = l * 4;
    int h = l >> 2;
    int dbase = (l & 3) * 4;

    float4 q = *(const float4*)&g_Qh[(size_t)dst * HIDD + c0];
    float4 kk = *(const float4*)&g_Kh[(size_t)src * HIDD + c0];
    uint2 ewu = *(const uint2*)&g_Eh[(size_t)e * 256 + c0];
    uint2 ebu = *(const uint2*)&g_Eh[(size_t)e * 256 + 128 + c0];
    float4 vv = *(const float4*)&g_Vh[(size_t)src * HIDD + c0];

    float2 ew01 = __half22float2(*(__half2*)&ewu.x);
    float2 ew23 = __half22float2(*(__half2*)&ewu.y);
    float2 eb01 = __half22float2(*(__half2*)&ebu.x);
    float2 eb23 = __half22float2(*(__half2*)&ebu.y);
    float ewf[4] = {ew01.x, ew01.y, ew23.x, ew23.y};
    float ebf[4] = {eb01.x, eb01.y, eb23.x, eb23.y};

    const float* qf = (const float*)&q;
    const float* kf = (const float*)&kk;
    const float* vf = (const float*)&vv;

    float ce[4];
    float part = 0.f;
#pragma unroll
    for (int i = 0; i < 4; i++) {
        float m = qf[i] + kf[i];
        float cc = m * ewf[i];
        float ss = sqrtf(fabsf(cc));
        ss = (cc >= 0.f) ? ss : -ss;          // signed sqrt
        float val = ss + ebf[i];
        ce[i] = fmaxf(val, 0.f);
        part += ce[i] * Aw[(dbase + i) * NH + h];
    }
    {
        uint2 cu;
        cu.x = pack_h2(ce[0], ce[1]);
        cu.y = pack_h2(ce[2], ce[3]);
        *(uint2*)&g_ce[(size_t)e * HIDD + c0] = cu;
    }

    part += __shfl_xor_sync(0xffffffffu, part, 1);
    part += __shfl_xor_sync(0xffffffffu, part, 2);
    float s = fminf(fmaxf(part, -5.f), 5.f);
    float p = __expf(s);

    if ((l & 3) == 0) atomicAdd(&g_ssum[(size_t)dst * NH + h], p);
    float4 av = make_float4(vf[0] * p, vf[1] * p, vf[2] * p, vf[3] * p);
    float4 rv = make_float4(ce[0] * p, ce[1] * p, ce[2] * p, ce[3] * p);
    atomicAdd((float4*)&g_agg[(size_t)dst * HIDD + c0], av);
    atomicAdd((float4*)&g_row[(size_t)dst * HIDD + c0], rv);
}

// ---------------- node pass: normalize, rowV = row @ Bw, deg scaling ----------------
__global__ void __launch_bounds__(256) node_kernel(const float* __restrict__ Bw,
                                                   const float* __restrict__ deg_coef,
                                                   const float* __restrict__ log_deg)
{
    __shared__ float rbuf[8][HIDD];
    int n = (int)((blockIdx.x * (size_t)blockDim.x + threadIdx.x) >> 5);
    int wl = (threadIdx.x >> 5) & 7;
    int l = threadIdx.x & 31;
    if (n >= NN) return;
    int h = l >> 2;
    int c0 = l * 4;

    float rs = 1.f / (g_ssum[(size_t)n * NH + h] + 1e-16f);
    float4 a = *(const float4*)&g_agg[(size_t)n * HIDD + c0];
    float4 r = *(const float4*)&g_row[(size_t)n * HIDD + c0];
    a.x *= rs; a.y *= rs; a.z *= rs; a.w *= rs;
    r.x *= rs; r.y *= rs; r.z *= rs; r.w *= rs;
    *(float4*)&rbuf[wl][c0] = r;
    __syncwarp();

    float4 q = *(const float4*)&g_Qh[(size_t)n * HIDD + c0];
    const float* af = (const float*)&a;
    const float* qf = (const float*)&q;
    float ld = log_deg[n];

    float out[4];
#pragma unroll
    for (int i = 0; i < 4; i++) {
        int c = c0 + i;
        float rv = 0.f;
#pragma unroll
        for (int d = 0; d < DDIM; d++)
            rv = fmaf(rbuf[wl][h * DDIM + d], __ldg(&Bw[d * HIDD + c]), rv);
        float ha = qf[i] + af[i] + rv;
        out[i] = ha * (deg_coef[2 * c] + ld * deg_coef[2 * c + 1]);
    }
    *(float4*)&g_hpre[(size_t)n * HIDD + c0] = make_float4(out[0], out[1], out[2], out[3]);
}

// ---------------- launch ----------------
extern "C" void kernel_launch(void* const* d_in, const int* in_sizes, int n_in,
                              void* d_out, int out_size)
{
    const float* x        = (const float*)d_in[0];
    const float* conn     = (const float*)d_in[1];
    const float* log_deg  = (const float*)d_in[2];
    const int*   ei       = (const int*)d_in[3];
    const float* WQ       = (const float*)d_in[4];
    const float* WK       = (const float*)d_in[5];
    const float* WV       = (const float*)d_in[6];
    const float* WE       = (const float*)d_in[7];
    const float* Aw       = (const float*)d_in[8];
    const float* Bw       = (const float*)d_in[9];
    const float* Ho_w     = (const float*)d_in[10];
    const float* Ho_b     = (const float*)d_in[11];
    const float* Eo_w     = (const float*)d_in[12];
    const float* Eo_b     = (const float*)d_in[13];
    const float* deg_coef = (const float*)d_in[14];
    const float* ln1h_g   = (const float*)d_in[15];
    const float* ln1h_b   = (const float*)d_in[16];
    const float* ln1e_g   = (const float*)d_in[17];
    const float* ln1e_b   = (const float*)d_in[18];
    const float* ln2h_g   = (const float*)d_in[19];
    const float* ln2h_b   = (const float*)d_in[20];
    const float* W1       = (const float*)d_in[21];
    const float* b1       = (const float*)d_in[22];
    const float* W2       = (const float*)d_in[23];
    const float* b2       = (const float*)d_in[24];

    float* out_h = (float*)d_out;
    float* out_e = out_h + (size_t)NN * HIDD;

    float *Qh, *Kh, *Vh, *ssum, *agg, *row, *hpre, *h1, *mlp;
    __half *Eh, *ce;
    cudaGetSymbolAddress((void**)&Qh, g_Qh);
    cudaGetSymbolAddress((void**)&Kh, g_Kh);
    cudaGetSymbolAddress((void**)&Vh, g_Vh);
    cudaGetSymbolAddress((void**)&Eh, g_Eh);
    cudaGetSymbolAddress((void**)&ce, g_ce);
    cudaGetSymbolAddress((void**)&ssum, g_ssum);
    cudaGetSymbolAddress((void**)&agg, g_agg);
    cudaGetSymbolAddress((void**)&row, g_row);
    cudaGetSymbolAddress((void**)&hpre, g_hpre);
    cudaGetSymbolAddress((void**)&h1, g_h1);
    cudaGetSymbolAddress((void**)&mlp, g_mlp);

    const int gN = (NN + 127) / 128;   // 391
    const int gE = (EE + 127) / 128;   // 4688

    cudaMemsetAsync(ssum, 0, (size_t)NN * NH * sizeof(float), 0);
    cudaMemsetAsync(agg, 0, (size_t)NN * HIDD * sizeof(float), 0);
    cudaMemsetAsync(row, 0, (size_t)NN * HIDD * sizeof(float), 0);

    // Qh, Kh, Vh  (fp32 A, fp32 C)
    tgemm<128, 0, false, false, false><<<dim3(gN, 1), 256>>>(x, WQ, 128, nullptr, nullptr, nullptr, nullptr, Qh, 128, NN);
    tgemm<128, 0, false, false, false><<<dim3(gN, 1), 256>>>(x, WK, 128, nullptr, nullptr, nullptr, nullptr, Kh, 128, NN);
    tgemm<128, 0, false, false, false><<<dim3(gN, 1), 256>>>(x, WV, 128, nullptr, nullptr, nullptr, nullptr, Vh, 128, NN);
    // Eh = conn @ WE  [E,256] fp16 out; grid swapped so n-split shares conn via L2
    tgemm<128, 0, false, true, true><<<dim3(2, gE), 256>>>(conn, WE, 256, nullptr, nullptr, nullptr, nullptr, Eh, 256, EE);

    // edge pass (conn_e + softmax-weighted segment sums)
    edge_kernel<<<(EE * 32 + 255) / 256, 256>>>(ei, Aw);
    // node pass -> h_pre
    node_kernel<<<(NN * 32 + 255) / 256, 256>>>(Bw, deg_coef, log_deg);

    // h1 = LN1h(x + hpre @ Ho_w + Ho_b)
    tgemm<128, 2, false, false, false><<<dim3(gN, 1), 256>>>(hpre, Ho_w, 128, Ho_b, x, ln1h_g, ln1h_b, h1, 128, NN);
    // mlp = relu(h1 @ W1 + b1); grid swapped for h1 L2 reuse
    tgemm<128, 1, false, false, true><<<dim3(2, gN), 256>>>(h1, W1, 256, b1, nullptr, nullptr, nullptr, mlp, 256, NN);
    // out_h = LN2h(h1 + mlp @ W2 + b2)
    tgemm<256, 2, false, false, false><<<dim3(gN, 1), 256>>>(mlp, W2, 128, b2, h1, ln2h_g, ln2h_b, out_h, 128, NN);
    // out_e = LN1e(conn + ce @ Eo_w + Eo_b); ce is fp16 A
    tgemm<128, 2, true, false, false><<<dim3(gE, 1), 256>>>(ce, Eo_w, 128, Eo_b, conn, ln1e_g, ln1e_b, out_e, 128, EE);
}

// round 15
// speedup vs baseline: 2.0719x; 1.1456x over previous
#include <cuda_runtime.h>
#include <cuda_fp16.h>
#include <cstdint>

#define NN 50000
#define EE 600000
#define HIDD 128
#define NH 8
#define DDIM 16

// ---------------- scratch (device globals; no allocation allowed) ----------------
__device__ __half g_Qh[(size_t)NN * HIDD];
__device__ __half g_Kh[(size_t)NN * HIDD];
__device__ __half g_Vh[(size_t)NN * HIDD];
__device__ __half g_ce[(size_t)EE * HIDD];  // conn_e / e_attn, fp16
__device__ float  g_ssum[(size_t)NN * NH];
__device__ float  g_agg[(size_t)NN * HIDD];
__device__ float  g_row[(size_t)NN * HIDD];
__device__ float  g_hpre[(size_t)NN * HIDD];
__device__ float  g_h1[(size_t)NN * HIDD];
__device__ float  g_mlp[(size_t)NN * 256];

__device__ __forceinline__ void mma16(float* c, const uint32_t* a, const uint32_t* b) {
    asm volatile(
        "mma.sync.aligned.m16n8k16.row.col.f32.f16.f16.f32 "
        "{%0,%1,%2,%3},{%4,%5,%6,%7},{%8,%9},{%0,%1,%2,%3};"
        : "+f"(c[0]), "+f"(c[1]), "+f"(c[2]), "+f"(c[3])
        : "r"(a[0]), "r"(a[1]), "r"(a[2]), "r"(a[3]), "r"(b[0]), "r"(b[1]));
}

__device__ __forceinline__ uint32_t pack_h2(float lo, float hi) {
    __half2 h = __floats2half2_rn(lo, hi);   // lo -> low half
    return *(uint32_t*)&h;
}

// ---------------- FP16 tensor-core GEMM (R14 winner, unchanged core) ------------
#define SMS 136
template <int KD, int EPI, bool AHALF, bool CHALF, bool SWAPG>
__global__ void __launch_bounds__(256, 2) tgemm(
    const void* __restrict__ Av, const float* __restrict__ W, int ldw,
    const float* __restrict__ bias, const float* __restrict__ resid,
    const float* __restrict__ lng, const float* __restrict__ lnb,
    void* __restrict__ Cv, int ldc, int M)
{
    const float*  Af = (const float*)Av;
    const __half* Ah = (const __half*)Av;
    float*  Cf = (float*)Cv;
    __half* Ch = (__half*)Cv;

    __shared__ uint32_t As2[2][8][SMS];
    __shared__ uint32_t Ws2[2][8][SMS];
    __shared__ float part[128][2][2];

    const int t = threadIdx.x;
    const int lane = t & 31;
    const int wid = t >> 5;
    const int wn = wid & 1;
    const int wm = wid >> 1;
    const int bxm = SWAPG ? blockIdx.y : blockIdx.x;
    const int bxn = SWAPG ? blockIdx.x : blockIdx.y;
    const int m0b = bxm * 128;
    const int n0 = bxn * 128;
    const int wm0 = wm * 32;
    const int wn0 = wn * 64;
    const int gr = lane >> 2;
    const int kq = lane & 3;

    float acc[2][8][4];
#pragma unroll
    for (int s = 0; s < 2; s++)
#pragma unroll
        for (int i = 0; i < 8; i++) { acc[s][i][0] = acc[s][i][1] = acc[s][i][2] = acc[s][i][3] = 0.f; }

    const int arow = t >> 2;
    const int acol = (t & 3) * 4;
    const int ak2 = acol >> 1;
    const int wj = t >> 5;
    const int wcol = (t & 31) * 4;

    float4 aRf[2]; uint2 aRh[2];
    float4 wRa, wRb;

    auto loadA = [&](int ko) {
#pragma unroll
        for (int p = 0; p < 2; p++) {
            int row = m0b + arow + p * 64;
            if (AHALF) {
                aRh[p] = make_uint2(0u, 0u);
                if (row < M) aRh[p] = *(const uint2*)&Ah[(size_t)row * KD + ko + acol];
            } else {
                aRf[p] = make_float4(0.f, 0.f, 0.f, 0.f);
                if (row < M) aRf[p] = *(const float4*)&Af[(size_t)row * KD + ko + acol];
            }
        }
    };
    auto loadW = [&](int ko) {
        wRa = *(const float4*)&W[(size_t)(ko + 2 * wj) * ldw + n0 + wcol];
        wRb = *(const float4*)&W[(size_t)(ko + 2 * wj + 1) * ldw + n0 + wcol];
    };
    auto stsAW = [&](int st) {
#pragma unroll
        for (int p = 0; p < 2; p++) {
            int m = arow + p * 64;
            if (AHALF) {
                As2[st][ak2 + 0][m] = aRh[p].x;
                As2[st][ak2 + 1][m] = aRh[p].y;
            } else {
                As2[st][ak2 + 0][m] = pack_h2(aRf[p].x, aRf[p].y);
                As2[st][ak2 + 1][m] = pack_h2(aRf[p].z, aRf[p].w);
            }
        }
        uint4 wv;
        wv.x = pack_h2(wRa.x, wRb.x); wv.y = pack_h2(wRa.y, wRb.y);
        wv.z = pack_h2(wRa.z, wRb.z); wv.w = pack_h2(wRa.w, wRb.w);
        *(uint4*)&Ws2[st][wj][wcol] = wv;
    };

    loadA(0); loadW(0); stsAW(0);

    int stage = 0;
    for (int kt = 0; kt < KD; kt += 16) {
        const bool has_next = (kt + 16 < KD);
        if (has_next) { loadA(kt + 16); loadW(kt + 16); }
        __syncthreads();
        {
            uint32_t a[2][4];
#pragma unroll
            for (int s = 0; s < 2; s++) {
                int mb = wm0 + s * 16;
                a[s][0] = As2[stage][kq][mb + gr];
                a[s][1] = As2[stage][kq][mb + 8 + gr];
                a[s][2] = As2[stage][kq + 4][mb + gr];
                a[s][3] = As2[stage][kq + 4][mb + 8 + gr];
            }
#pragma unroll
            for (int nf = 0; nf < 8; nf++) {
                uint32_t b[2];
                b[0] = Ws2[stage][kq][wn0 + nf * 8 + gr];
                b[1] = Ws2[stage][kq + 4][wn0 + nf * 8 + gr];
                mma16(acc[0][nf], a[0], b);
                mma16(acc[1][nf], a[1], b);
            }
        }
        if (has_next) stsAW(stage ^ 1);
        stage ^= 1;
    }

    if (EPI == 0 || EPI == 1) {
#pragma unroll
        for (int s = 0; s < 2; s++)
#pragma unroll
        for (int half = 0; half < 2; half++) {
            int r = m0b + wm0 + s * 16 + gr + half * 8;
            if (r >= M) continue;
#pragma unroll
            for (int nf = 0; nf < 8; nf++) {
                int c = n0 + wn0 + nf * 8 + 2 * kq;
                float v0 = acc[s][nf][half * 2 + 0];
                float v1 = acc[s][nf][half * 2 + 1];
                if (bias) { v0 += bias[c]; v1 += bias[c + 1]; }
                if (EPI == 1) { v0 = fmaxf(v0, 0.f); v1 = fmaxf(v1, 0.f); }
                if (CHALF) {
                    *(uint32_t*)&Ch[(size_t)r * ldc + c] = pack_h2(v0, v1);
                } else {
                    *(float2*)&Cf[(size_t)r * ldc + c] = make_float2(v0, v1);
                }
            }
        }
    } else {
        float v[2][2][16];
#pragma unroll
        for (int s = 0; s < 2; s++)
#pragma unroll
        for (int half = 0; half < 2; half++) {
            int r = m0b + wm0 + s * 16 + gr + half * 8;
            bool ok = (r < M);
            float sm = 0.f, s2 = 0.f;
#pragma unroll
            for (int nf = 0; nf < 8; nf++) {
                int c = wn0 + nf * 8 + 2 * kq;
                float x0 = acc[s][nf][half * 2 + 0] + bias[c];
                float x1 = acc[s][nf][half * 2 + 1] + bias[c + 1];
                if (ok) {
                    float2 rr = *(const float2*)&resid[(size_t)r * 128 + c];
                    x0 += rr.x; x1 += rr.y;
                }
                v[s][half][2 * nf] = x0; v[s][half][2 * nf + 1] = x1;
                sm += x0 + x1;
                s2 += x0 * x0 + x1 * x1;
            }
#pragma unroll
            for (int off = 1; off < 4; off <<= 1) {
                sm += __shfl_xor_sync(0xffffffffu, sm, off);
                s2 += __shfl_xor_sync(0xffffffffu, s2, off);
            }
            if (kq == 0) {
                int lr = wm0 + s * 16 + gr + half * 8;
                part[lr][wn][0] = sm;
                part[lr][wn][1] = s2;
            }
        }
        __syncthreads();
#pragma unroll
        for (int s = 0; s < 2; s++)
#pragma unroll
        for (int half = 0; half < 2; half++) {
            int lr = wm0 + s * 16 + gr + half * 8;
            int r = m0b + lr;
            if (r >= M) continue;
            float sm = part[lr][0][0] + part[lr][1][0];
            float s2 = part[lr][0][1] + part[lr][1][1];
            float mean = sm * (1.f / 128.f);
            float var = s2 * (1.f / 128.f) - mean * mean;
            float rstd = rsqrtf(var + 1e-5f);
#pragma unroll
            for (int nf = 0; nf < 8; nf++) {
                int c = wn0 + nf * 8 + 2 * kq;
                float o0 = (v[s][half][2 * nf] - mean) * rstd * lng[c] + lnb[c];
                float o1 = (v[s][half][2 * nf + 1] - mean) * rstd * lng[c + 1] + lnb[c + 1];
                *(float2*)&Cf[(size_t)r * 128 + c] = make_float2(o0, o1);
            }
        }
    }
}

// ---------------- fused Eh-GEMM + edge pass ----------------
// CTA = 64 edges x 256 cols (full [Ew|Eb]).  8 warps in 2m x 4n, warp tile 32x64.
// Same double-buffered mainloop as tgemm (re-tiled loaders), acc stays 64 regs.
// Epilogue: acc -> fp16 smem ebuf -> in-block edge math (signed-sqrt/relu,
// softmax weights, segment atomics).  Eh never touches gmem.
// Dynamic smem: As2 2*8*76 | Ws2 2*8*264 | ebuf 64*132  (uint32) = 55552 B
#define ASZ (2 * 8 * 76)
#define WSZ (2 * 8 * 264)
#define EBS 132
#define FUS_SMEM ((ASZ + WSZ + 64 * EBS) * 4)

__global__ void __launch_bounds__(256, 2) eh_edge_gemm(
    const float* __restrict__ conn, const float* __restrict__ WE,
    const int* __restrict__ ei, const float* __restrict__ Aw)
{
    extern __shared__ uint32_t dsm[];
    uint32_t* As2 = dsm;                 // [st][k2][m] : st*608 + k2*76 + m
    uint32_t* Ws2 = dsm + ASZ;           // [st][k2][n] : st*2112 + k2*264 + n
    uint32_t* ebuf = dsm + ASZ + WSZ;    // [r][c2]     : r*132 + c2

    const int t = threadIdx.x;
    const int lane = t & 31;
    const int wid = t >> 5;            // 0..7
    const int wn = wid & 3;            // n quarter (64 cols)
    const int wm = wid >> 2;           // m half (32 rows)
    const int e0 = blockIdx.x * 64;    // EE % 64 == 0
    const int wm0 = wm * 32;
    const int wn0 = wn * 64;
    const int gr = lane >> 2;
    const int kq = lane & 3;

    float acc[2][8][4];
#pragma unroll
    for (int s = 0; s < 2; s++)
#pragma unroll
        for (int i = 0; i < 8; i++) { acc[s][i][0] = acc[s][i][1] = acc[s][i][2] = acc[s][i][3] = 0.f; }

    // loaders: A = conn rows e0..e0+63 (one float4/thread), W = 16x256 (4 float4/thread)
    const int arow = t >> 2;           // 0..63
    const int acol = (t & 3) * 4;
    const int ak2 = acol >> 1;
    const int wp = t >> 6;             // 0..3 : k-row pairs (2wp,2wp+1) and (+8)
    const int wc4 = (t & 63) * 4;      // 0..252

    float4 aRf;
    float4 wRa0, wRb0, wRa1, wRb1;

    auto loadA = [&](int ko) {
        aRf = *(const float4*)&conn[(size_t)(e0 + arow) * 128 + ko + acol];
    };
    auto loadW = [&](int ko) {
        wRa0 = *(const float4*)&WE[(size_t)(ko + 2 * wp) * 256 + wc4];
        wRb0 = *(const float4*)&WE[(size_t)(ko + 2 * wp + 1) * 256 + wc4];
        wRa1 = *(const float4*)&WE[(size_t)(ko + 2 * wp + 8) * 256 + wc4];
        wRb1 = *(const float4*)&WE[(size_t)(ko + 2 * wp + 9) * 256 + wc4];
    };
    auto stsAW = [&](int st) {
        As2[st * 608 + (ak2 + 0) * 76 + arow] = pack_h2(aRf.x, aRf.y);
        As2[st * 608 + (ak2 + 1) * 76 + arow] = pack_h2(aRf.z, aRf.w);
        uint4 wv;
        wv.x = pack_h2(wRa0.x, wRb0.x); wv.y = pack_h2(wRa0.y, wRb0.y);
        wv.z = pack_h2(wRa0.z, wRb0.z); wv.w = pack_h2(wRa0.w, wRb0.w);
        *(uint4*)&Ws2[st * 2112 + wp * 264 + wc4] = wv;
        wv.x = pack_h2(wRa1.x, wRb1.x); wv.y = pack_h2(wRa1.y, wRb1.y);
        wv.z = pack_h2(wRa1.z, wRb1.z); wv.w = pack_h2(wRa1.w, wRb1.w);
        *(uint4*)&Ws2[st * 2112 + (wp + 4) * 264 + wc4] = wv;
    };

    loadA(0); loadW(0); stsAW(0);

    int stage = 0;
    for (int kt = 0; kt < 128; kt += 16) {
        const bool has_next = (kt + 16 < 128);
        if (has_next) { loadA(kt + 16); loadW(kt + 16); }
        __syncthreads();
        {
            uint32_t a[2][4];
#pragma unroll
            for (int s = 0; s < 2; s++) {
                int mb = wm0 + s * 16;
                a[s][0] = As2[stage * 608 + kq * 76 + mb + gr];
                a[s][1] = As2[stage * 608 + kq * 76 + mb + 8 + gr];
                a[s][2] = As2[stage * 608 + (kq + 4) * 76 + mb + gr];
                a[s][3] = As2[stage * 608 + (kq + 4) * 76 + mb + 8 + gr];
            }
#pragma unroll
            for (int nf = 0; nf < 8; nf++) {
                uint32_t b[2];
                b[0] = Ws2[stage * 2112 + kq * 264 + wn0 + nf * 8 + gr];
                b[1] = Ws2[stage * 2112 + (kq + 4) * 264 + wn0 + nf * 8 + gr];
                mma16(acc[0][nf], a[0], b);
                mma16(acc[1][nf], a[1], b);
            }
        }
        if (has_next) stsAW(stage ^ 1);
        stage ^= 1;
    }

    // stash Eh tile (fp16) into ebuf: half2 col index = wn*32 + nf*4 + kq
#pragma unroll
    for (int s = 0; s < 2; s++)
#pragma unroll
    for (int half = 0; half < 2; half++) {
        int r = wm0 + s * 16 + gr + half * 8;
#pragma unroll
        for (int nf = 0; nf < 8; nf++) {
            ebuf[r * EBS + wn * 32 + nf * 4 + kq] =
                pack_h2(acc[s][nf][half * 2 + 0], acc[s][nf][half * 2 + 1]);
        }
    }
    __syncthreads();

    // edge phase: warp w handles edges w*8 .. w*8+7 (2 batches of 4)
    {
        const int c0 = lane * 4;
        const int h = lane >> 2;
        const int dbase = (lane & 3) * 4;
        float aw[4];
#pragma unroll
        for (int i = 0; i < 4; i++) aw[i] = Aw[(dbase + i) * NH + h];

#pragma unroll
        for (int g = 0; g < 2; g++) {
            int dstA[4], srcA[4];
            uint2 qA[4], kA[4], vA[4];
#pragma unroll
            for (int i = 0; i < 4; i++) {
                int e = e0 + wid * 8 + g * 4 + i;
                dstA[i] = ei[e];
                srcA[i] = ei[EE + e];
            }
#pragma unroll
            for (int i = 0; i < 4; i++) {
                qA[i] = *(const uint2*)&g_Qh[(size_t)dstA[i] * HIDD + c0];
                kA[i] = *(const uint2*)&g_Kh[(size_t)srcA[i] * HIDD + c0];
                vA[i] = *(const uint2*)&g_Vh[(size_t)srcA[i] * HIDD + c0];
            }
#pragma unroll
            for (int i = 0; i < 4; i++) {
                int r = wid * 8 + g * 4 + i;
                int e = e0 + r;
                uint2 ewu = *(const uint2*)&ebuf[r * EBS + lane * 2];
                uint2 ebu = *(const uint2*)&ebuf[r * EBS + 64 + lane * 2];
                float2 ew01 = __half22float2(*(__half2*)&ewu.x);
                float2 ew23 = __half22float2(*(__half2*)&ewu.y);
                float2 eb01 = __half22float2(*(__half2*)&ebu.x);
                float2 eb23 = __half22float2(*(__half2*)&ebu.y);
                float2 q01 = __half22float2(*(__half2*)&qA[i].x);
                float2 q23 = __half22float2(*(__half2*)&qA[i].y);
                float2 k01 = __half22float2(*(__half2*)&kA[i].x);
                float2 k23 = __half22float2(*(__half2*)&kA[i].y);
                float2 v01 = __half22float2(*(__half2*)&vA[i].x);
                float2 v23 = __half22float2(*(__half2*)&vA[i].y);
                float ewf[4] = {ew01.x, ew01.y, ew23.x, ew23.y};
                float ebf[4] = {eb01.x, eb01.y, eb23.x, eb23.y};
                float qf[4] = {q01.x, q01.y, q23.x, q23.y};
                float kf[4] = {k01.x, k01.y, k23.x, k23.y};
                float vf[4] = {v01.x, v01.y, v23.x, v23.y};

                float ce[4];
                float part = 0.f;
#pragma unroll
                for (int j = 0; j < 4; j++) {
                    float m = qf[j] + kf[j];
                    float cc = m * ewf[j];
                    float ss = sqrtf(fabsf(cc));
                    ss = (cc >= 0.f) ? ss : -ss;      // signed sqrt
                    ce[j] = fmaxf(ss + ebf[j], 0.f);
                    part += ce[j] * aw[j];
                }
                uint2 cu;
                cu.x = pack_h2(ce[0], ce[1]);
                cu.y = pack_h2(ce[2], ce[3]);
                *(uint2*)&g_ce[(size_t)e * HIDD + c0] = cu;

                part += __shfl_xor_sync(0xffffffffu, part, 1);
                part += __shfl_xor_sync(0xffffffffu, part, 2);
                float s = fminf(fmaxf(part, -5.f), 5.f);
                float p = __expf(s);

                if ((lane & 3) == 0) atomicAdd(&g_ssum[(size_t)dstA[i] * NH + h], p);
                float4 av = make_float4(vf[0] * p, vf[1] * p, vf[2] * p, vf[3] * p);
                float4 rv = make_float4(ce[0] * p, ce[1] * p, ce[2] * p, ce[3] * p);
                atomicAdd((float4*)&g_agg[(size_t)dstA[i] * HIDD + c0], av);
                atomicAdd((float4*)&g_row[(size_t)dstA[i] * HIDD + c0], rv);
            }
        }
    }
}

// ---------------- node pass: normalize, rowV = row @ Bw, deg scaling ----------------
__global__ void __launch_bounds__(256) node_kernel(const float* __restrict__ Bw,
                                                   const float* __restrict__ deg_coef,
                                                   const float* __restrict__ log_deg)
{
    __shared__ float rbuf[8][HIDD];
    int n = (int)((blockIdx.x * (size_t)blockDim.x + threadIdx.x) >> 5);
    int wl = (threadIdx.x >> 5) & 7;
    int l = threadIdx.x & 31;
    if (n >= NN) return;
    int h = l >> 2;
    int c0 = l * 4;

    float rs = 1.f / (g_ssum[(size_t)n * NH + h] + 1e-16f);
    float4 a = *(const float4*)&g_agg[(size_t)n * HIDD + c0];
    float4 r = *(const float4*)&g_row[(size_t)n * HIDD + c0];
    a.x *= rs; a.y *= rs; a.z *= rs; a.w *= rs;
    r.x *= rs; r.y *= rs; r.z *= rs; r.w *= rs;
    *(float4*)&rbuf[wl][c0] = r;
    __syncwarp();

    uint2 qu = *(const uint2*)&g_Qh[(size_t)n * HIDD + c0];
    float2 q01 = __half22float2(*(__half2*)&qu.x);
    float2 q23 = __half22float2(*(__half2*)&qu.y);
    float qf[4] = {q01.x, q01.y, q23.x, q23.y};
    const float* af = (const float*)&a;
    float ld = log_deg[n];

    float out[4];
#pragma unroll
    for (int i = 0; i < 4; i++) {
        int c = c0 + i;
        float rv = 0.f;
#pragma unroll
        for (int d = 0; d < DDIM; d++)
            rv = fmaf(rbuf[wl][h * DDIM + d], __ldg(&Bw[d * HIDD + c]), rv);
        float ha = qf[i] + af[i] + rv;
        out[i] = ha * (deg_coef[2 * c] + ld * deg_coef[2 * c + 1]);
    }
    *(float4*)&g_hpre[(size_t)n * HIDD + c0] = make_float4(out[0], out[1], out[2], out[3]);
}

// ---------------- launch ----------------
extern "C" void kernel_launch(void* const* d_in, const int* in_sizes, int n_in,
                              void* d_out, int out_size)
{
    const float* x        = (const float*)d_in[0];
    const float* conn     = (const float*)d_in[1];
    const float* log_deg  = (const float*)d_in[2];
    const int*   ei       = (const int*)d_in[3];
    const float* WQ       = (const float*)d_in[4];
    const float* WK       = (const float*)d_in[5];
    const float* WV       = (const float*)d_in[6];
    const float* WE       = (const float*)d_in[7];
    const float* Aw       = (const float*)d_in[8];
    const float* Bw       = (const float*)d_in[9];
    const float* Ho_w     = (const float*)d_in[10];
    const float* Ho_b     = (const float*)d_in[11];
    const float* Eo_w     = (const float*)d_in[12];
    const float* Eo_b     = (const float*)d_in[13];
    const float* deg_coef = (const float*)d_in[14];
    const float* ln1h_g   = (const float*)d_in[15];
    const float* ln1h_b   = (const float*)d_in[16];
    const float* ln1e_g   = (const float*)d_in[17];
    const float* ln1e_b   = (const float*)d_in[18];
    const float* ln2h_g   = (const float*)d_in[19];
    const float* ln2h_b   = (const float*)d_in[20];
    const float* W1       = (const float*)d_in[21];
    const float* b1       = (const float*)d_in[22];
    const float* W2       = (const float*)d_in[23];
    const float* b2       = (const float*)d_in[24];

    float* out_h = (float*)d_out;
    float* out_e = out_h + (size_t)NN * HIDD;

    float *ssum, *agg, *row, *hpre, *h1, *mlp;
    __half *Qh, *Kh, *Vh, *ce;
    cudaGetSymbolAddress((void**)&Qh, g_Qh);
    cudaGetSymbolAddress((void**)&Kh, g_Kh);
    cudaGetSymbolAddress((void**)&Vh, g_Vh);
    cudaGetSymbolAddress((void**)&ce, g_ce);
    cudaGetSymbolAddress((void**)&ssum, g_ssum);
    cudaGetSymbolAddress((void**)&agg, g_agg);
    cudaGetSymbolAddress((void**)&row, g_row);
    cudaGetSymbolAddress((void**)&hpre, g_hpre);
    cudaGetSymbolAddress((void**)&h1, g_h1);
    cudaGetSymbolAddress((void**)&mlp, g_mlp);

    cudaFuncSetAttribute(eh_edge_gemm, cudaFuncAttributeMaxDynamicSharedMemorySize, FUS_SMEM);

    const int gN = (NN + 127) / 128;   // 391
    const int gE = (EE + 127) / 128;   // 4688

    cudaMemsetAsync(ssum, 0, (size_t)NN * NH * sizeof(float), 0);
    cudaMemsetAsync(agg, 0, (size_t)NN * HIDD * sizeof(float), 0);
    cudaMemsetAsync(row, 0, (size_t)NN * HIDD * sizeof(float), 0);

    // Qh, Kh, Vh (fp32 A, fp16 C)
    tgemm<128, 0, false, true, false><<<dim3(gN, 1), 256>>>(x, WQ, 128, nullptr, nullptr, nullptr, nullptr, Qh, 128, NN);
    tgemm<128, 0, false, true, false><<<dim3(gN, 1), 256>>>(x, WK, 128, nullptr, nullptr, nullptr, nullptr, Kh, 128, NN);
    tgemm<128, 0, false, true, false><<<dim3(gN, 1), 256>>>(x, WV, 128, nullptr, nullptr, nullptr, nullptr, Vh, 128, NN);

    // fused Eh GEMM + edge pass (Eh never hits gmem)
    eh_edge_gemm<<<EE / 64, 256, FUS_SMEM>>>(conn, WE, ei, Aw);

    // node pass -> h_pre
    node_kernel<<<(NN * 32 + 255) / 256, 256>>>(Bw, deg_coef, log_deg);

    // h1 = LN1h(x + hpre @ Ho_w + Ho_b)
    tgemm<128, 2, false, false, false><<<dim3(gN, 1), 256>>>(hpre, Ho_w, 128, Ho_b, x, ln1h_g, ln1h_b, h1, 128, NN);
    // mlp = relu(h1 @ W1 + b1); grid swapped for h1 L2 reuse
    tgemm<128, 1, false, false, true><<<dim3(2, gN), 256>>>(h1, W1, 256, b1, nullptr, nullptr, nullptr, mlp, 256, NN);
    // out_h = LN2h(h1 + mlp @ W2 + b2)
    tgemm<256, 2, false, false, false><<<dim3(gN, 1), 256>>>(mlp, W2, 128, b2, h1, ln2h_g, ln2h_b, out_h, 128, NN);
    // out_e = LN1e(conn + ce @ Eo_w + Eo_b); ce is fp16 A
    tgemm<128, 2, true, false, false><<<dim3(gE, 1), 256>>>(ce, Eo_w, 128, Eo_b, conn, ln1e_g, ln1e_b, out_e, 128, EE);
}

// round 16
// speedup vs baseline: 2.2121x; 1.0677x over previous
#include <cuda_runtime.h>
#include <cuda_fp16.h>
#include <cstdint>

#define NN 50000
#define EE 600000
#define HIDD 128
#define NH 8
#define DDIM 16

// ---------------- scratch (device globals; no allocation allowed) ----------------
__device__ __half g_Qh[(size_t)NN * HIDD];
__device__ __half g_Kh[(size_t)NN * HIDD];
__device__ __half g_Vh[(size_t)NN * HIDD];
__device__ float  g_ssum[(size_t)NN * NH];
__device__ float  g_agg[(size_t)NN * HIDD];
__device__ float  g_row[(size_t)NN * HIDD];
__device__ float  g_hpre[(size_t)NN * HIDD];
__device__ float  g_h1[(size_t)NN * HIDD];
__device__ float  g_mlp[(size_t)NN * 256];

__device__ __forceinline__ void mma16(float* c, const uint32_t* a, const uint32_t* b) {
    asm volatile(
        "mma.sync.aligned.m16n8k16.row.col.f32.f16.f16.f32 "
        "{%0,%1,%2,%3},{%4,%5,%6,%7},{%8,%9},{%0,%1,%2,%3};"
        : "+f"(c[0]), "+f"(c[1]), "+f"(c[2]), "+f"(c[3])
        : "r"(a[0]), "r"(a[1]), "r"(a[2]), "r"(a[3]), "r"(b[0]), "r"(b[1]));
}

__device__ __forceinline__ uint32_t pack_h2(float lo, float hi) {
    __half2 h = __floats2half2_rn(lo, hi);   // lo -> low half
    return *(uint32_t*)&h;
}

// ---------------- FP16 tensor-core GEMM (R14 winner, unchanged core) ------------
#define SMS 136
template <int KD, int EPI, bool AHALF, bool CHALF, bool SWAPG>
__global__ void __launch_bounds__(256, 2) tgemm(
    const void* __restrict__ Av, const float* __restrict__ W, int ldw,
    const float* __restrict__ bias, const float* __restrict__ resid,
    const float* __restrict__ lng, const float* __restrict__ lnb,
    void* __restrict__ Cv, int ldc, int M)
{
    const float*  Af = (const float*)Av;
    const __half* Ah = (const __half*)Av;
    float*  Cf = (float*)Cv;
    __half* Ch = (__half*)Cv;

    __shared__ uint32_t As2[2][8][SMS];
    __shared__ uint32_t Ws2[2][8][SMS];
    __shared__ float part[128][2][2];

    const int t = threadIdx.x;
    const int lane = t & 31;
    const int wid = t >> 5;
    const int wn = wid & 1;
    const int wm = wid >> 1;
    const int bxm = SWAPG ? blockIdx.y : blockIdx.x;
    const int bxn = SWAPG ? blockIdx.x : blockIdx.y;
    const int m0b = bxm * 128;
    const int n0 = bxn * 128;
    const int wm0 = wm * 32;
    const int wn0 = wn * 64;
    const int gr = lane >> 2;
    const int kq = lane & 3;

    float acc[2][8][4];
#pragma unroll
    for (int s = 0; s < 2; s++)
#pragma unroll
        for (int i = 0; i < 8; i++) { acc[s][i][0] = acc[s][i][1] = acc[s][i][2] = acc[s][i][3] = 0.f; }

    const int arow = t >> 2;
    const int acol = (t & 3) * 4;
    const int ak2 = acol >> 1;
    const int wj = t >> 5;
    const int wcol = (t & 31) * 4;

    float4 aRf[2]; uint2 aRh[2];
    float4 wRa, wRb;

    auto loadA = [&](int ko) {
#pragma unroll
        for (int p = 0; p < 2; p++) {
            int row = m0b + arow + p * 64;
            if (AHALF) {
                aRh[p] = make_uint2(0u, 0u);
                if (row < M) aRh[p] = *(const uint2*)&Ah[(size_t)row * KD + ko + acol];
            } else {
                aRf[p] = make_float4(0.f, 0.f, 0.f, 0.f);
                if (row < M) aRf[p] = *(const float4*)&Af[(size_t)row * KD + ko + acol];
            }
        }
    };
    auto loadW = [&](int ko) {
        wRa = *(const float4*)&W[(size_t)(ko + 2 * wj) * ldw + n0 + wcol];
        wRb = *(const float4*)&W[(size_t)(ko + 2 * wj + 1) * ldw + n0 + wcol];
    };
    auto stsAW = [&](int st) {
#pragma unroll
        for (int p = 0; p < 2; p++) {
            int m = arow + p * 64;
            if (AHALF) {
                As2[st][ak2 + 0][m] = aRh[p].x;
                As2[st][ak2 + 1][m] = aRh[p].y;
            } else {
                As2[st][ak2 + 0][m] = pack_h2(aRf[p].x, aRf[p].y);
                As2[st][ak2 + 1][m] = pack_h2(aRf[p].z, aRf[p].w);
            }
        }
        uint4 wv;
        wv.x = pack_h2(wRa.x, wRb.x); wv.y = pack_h2(wRa.y, wRb.y);
        wv.z = pack_h2(wRa.z, wRb.z); wv.w = pack_h2(wRa.w, wRb.w);
        *(uint4*)&Ws2[st][wj][wcol] = wv;
    };

    loadA(0); loadW(0); stsAW(0);

    int stage = 0;
    for (int kt = 0; kt < KD; kt += 16) {
        const bool has_next = (kt + 16 < KD);
        if (has_next) { loadA(kt + 16); loadW(kt + 16); }
        __syncthreads();
        {
            uint32_t a[2][4];
#pragma unroll
            for (int s = 0; s < 2; s++) {
                int mb = wm0 + s * 16;
                a[s][0] = As2[stage][kq][mb + gr];
                a[s][1] = As2[stage][kq][mb + 8 + gr];
                a[s][2] = As2[stage][kq + 4][mb + gr];
                a[s][3] = As2[stage][kq + 4][mb + 8 + gr];
            }
#pragma unroll
            for (int nf = 0; nf < 8; nf++) {
                uint32_t b[2];
                b[0] = Ws2[stage][kq][wn0 + nf * 8 + gr];
                b[1] = Ws2[stage][kq + 4][wn0 + nf * 8 + gr];
                mma16(acc[0][nf], a[0], b);
                mma16(acc[1][nf], a[1], b);
            }
        }
        if (has_next) stsAW(stage ^ 1);
        stage ^= 1;
    }

    if (EPI == 0 || EPI == 1) {
#pragma unroll
        for (int s = 0; s < 2; s++)
#pragma unroll
        for (int half = 0; half < 2; half++) {
            int r = m0b + wm0 + s * 16 + gr + half * 8;
            if (r >= M) continue;
#pragma unroll
            for (int nf = 0; nf < 8; nf++) {
                int c = n0 + wn0 + nf * 8 + 2 * kq;
                float v0 = acc[s][nf][half * 2 + 0];
                float v1 = acc[s][nf][half * 2 + 1];
                if (bias) { v0 += bias[c]; v1 += bias[c + 1]; }
                if (EPI == 1) { v0 = fmaxf(v0, 0.f); v1 = fmaxf(v1, 0.f); }
                if (CHALF) {
                    *(uint32_t*)&Ch[(size_t)r * ldc + c] = pack_h2(v0, v1);
                } else {
                    *(float2*)&Cf[(size_t)r * ldc + c] = make_float2(v0, v1);
                }
            }
        }
    } else {
        float v[2][2][16];
#pragma unroll
        for (int s = 0; s < 2; s++)
#pragma unroll
        for (int half = 0; half < 2; half++) {
            int r = m0b + wm0 + s * 16 + gr + half * 8;
            bool ok = (r < M);
            float sm = 0.f, s2 = 0.f;
#pragma unroll
            for (int nf = 0; nf < 8; nf++) {
                int c = wn0 + nf * 8 + 2 * kq;
                float x0 = acc[s][nf][half * 2 + 0] + bias[c];
                float x1 = acc[s][nf][half * 2 + 1] + bias[c + 1];
                if (ok) {
                    float2 rr = *(const float2*)&resid[(size_t)r * 128 + c];
                    x0 += rr.x; x1 += rr.y;
                }
                v[s][half][2 * nf] = x0; v[s][half][2 * nf + 1] = x1;
                sm += x0 + x1;
                s2 += x0 * x0 + x1 * x1;
            }
#pragma unroll
            for (int off = 1; off < 4; off <<= 1) {
                sm += __shfl_xor_sync(0xffffffffu, sm, off);
                s2 += __shfl_xor_sync(0xffffffffu, s2, off);
            }
            if (kq == 0) {
                int lr = wm0 + s * 16 + gr + half * 8;
                part[lr][wn][0] = sm;
                part[lr][wn][1] = s2;
            }
        }
        __syncthreads();
#pragma unroll
        for (int s = 0; s < 2; s++)
#pragma unroll
        for (int half = 0; half < 2; half++) {
            int lr = wm0 + s * 16 + gr + half * 8;
            int r = m0b + lr;
            if (r >= M) continue;
            float sm = part[lr][0][0] + part[lr][1][0];
            float s2 = part[lr][0][1] + part[lr][1][1];
            float mean = sm * (1.f / 128.f);
            float var = s2 * (1.f / 128.f) - mean * mean;
            float rstd = rsqrtf(var + 1e-5f);
#pragma unroll
            for (int nf = 0; nf < 8; nf++) {
                int c = wn0 + nf * 8 + 2 * kq;
                float o0 = (v[s][half][2 * nf] - mean) * rstd * lng[c] + lnb[c];
                float o1 = (v[s][half][2 * nf + 1] - mean) * rstd * lng[c + 1] + lnb[c + 1];
                *(float2*)&Cf[(size_t)r * 128 + c] = make_float2(o0, o1);
            }
        }
    }
}

// ---------------- fused Eh-GEMM + edge pass + Eo-GEMM + LN1e --------------------
// CTA = 64 edges.  Phase 1: Eh = conn@WE (256 cols) -> ebuf (fp16).
// Phase 2: edge math in-block (ce overwrites ebuf cols 0..127; atomics).
// Phase 3: out_e = LN1e(conn + ce@Eo_w + Eo_b), A-fragments straight from ebuf,
//          Eo_w double-buffered through Ws2 (reused).  ce never touches gmem.
// smem (uint32): As2 2*8*76 | Ws2 2*8*264 | ebuf 64*132 | part2 64*8 floats
#define ASZ (2 * 8 * 76)
#define WSZ (2 * 8 * 264)
#define EBS 132
#define FUS_SMEM (((ASZ + WSZ + 64 * EBS) + 64 * 8) * 4)

__global__ void __launch_bounds__(256, 2) eh_edge_gemm(
    const float* __restrict__ conn, const float* __restrict__ WE,
    const int* __restrict__ ei, const float* __restrict__ Aw,
    const float* __restrict__ Eo_w, const float* __restrict__ Eo_b,
    const float* __restrict__ ln1e_g, const float* __restrict__ ln1e_b,
    float* __restrict__ out_e)
{
    extern __shared__ uint32_t dsm[];
    uint32_t* As2 = dsm;                 // [st][k2][m] : st*608 + k2*76 + m
    uint32_t* Ws2 = dsm + ASZ;           // [st][k2][n] : st*2112 + k2*264 + n
    uint32_t* ebuf = dsm + ASZ + WSZ;    // [r][c2]     : r*132 + c2
    float* part2 = (float*)(dsm + ASZ + WSZ + 64 * EBS);   // [r][wn][2] : r*8+wn*2

    const int t = threadIdx.x;
    const int lane = t & 31;
    const int wid = t >> 5;            // 0..7
    const int wn = wid & 3;            // n quarter
    const int wm = wid >> 2;           // m half (32 rows)
    const int e0 = blockIdx.x * 64;    // EE % 64 == 0
    const int wm0 = wm * 32;
    const int wn0 = wn * 64;
    const int gr = lane >> 2;
    const int kq = lane & 3;

    float acc[2][8][4];
#pragma unroll
    for (int s = 0; s < 2; s++)
#pragma unroll
        for (int i = 0; i < 8; i++) { acc[s][i][0] = acc[s][i][1] = acc[s][i][2] = acc[s][i][3] = 0.f; }

    const int arow = t >> 2;           // 0..63
    const int acol = (t & 3) * 4;
    const int ak2 = acol >> 1;
    const int wp = t >> 6;             // 0..3
    const int wc4 = (t & 63) * 4;      // 0..252

    float4 aRf;
    float4 wRa0, wRb0, wRa1, wRb1;

    auto loadA = [&](int ko) {
        aRf = *(const float4*)&conn[(size_t)(e0 + arow) * 128 + ko + acol];
    };
    auto loadW = [&](int ko) {
        wRa0 = *(const float4*)&WE[(size_t)(ko + 2 * wp) * 256 + wc4];
        wRb0 = *(const float4*)&WE[(size_t)(ko + 2 * wp + 1) * 256 + wc4];
        wRa1 = *(const float4*)&WE[(size_t)(ko + 2 * wp + 8) * 256 + wc4];
        wRb1 = *(const float4*)&WE[(size_t)(ko + 2 * wp + 9) * 256 + wc4];
    };
    auto stsAW = [&](int st) {
        As2[st * 608 + (ak2 + 0) * 76 + arow] = pack_h2(aRf.x, aRf.y);
        As2[st * 608 + (ak2 + 1) * 76 + arow] = pack_h2(aRf.z, aRf.w);
        uint4 wv;
        wv.x = pack_h2(wRa0.x, wRb0.x); wv.y = pack_h2(wRa0.y, wRb0.y);
        wv.z = pack_h2(wRa0.z, wRb0.z); wv.w = pack_h2(wRa0.w, wRb0.w);
        *(uint4*)&Ws2[st * 2112 + wp * 264 + wc4] = wv;
        wv.x = pack_h2(wRa1.x, wRb1.x); wv.y = pack_h2(wRa1.y, wRb1.y);
        wv.z = pack_h2(wRa1.z, wRb1.z); wv.w = pack_h2(wRa1.w, wRb1.w);
        *(uint4*)&Ws2[st * 2112 + (wp + 4) * 264 + wc4] = wv;
    };

    loadA(0); loadW(0); stsAW(0);

    int stage = 0;
    for (int kt = 0; kt < 128; kt += 16) {
        const bool has_next = (kt + 16 < 128);
        if (has_next) { loadA(kt + 16); loadW(kt + 16); }
        __syncthreads();
        {
            uint32_t a[2][4];
#pragma unroll
            for (int s = 0; s < 2; s++) {
                int mb = wm0 + s * 16;
                a[s][0] = As2[stage * 608 + kq * 76 + mb + gr];
                a[s][1] = As2[stage * 608 + kq * 76 + mb + 8 + gr];
                a[s][2] = As2[stage * 608 + (kq + 4) * 76 + mb + gr];
                a[s][3] = As2[stage * 608 + (kq + 4) * 76 + mb + 8 + gr];
            }
#pragma unroll
            for (int nf = 0; nf < 8; nf++) {
                uint32_t b[2];
                b[0] = Ws2[stage * 2112 + kq * 264 + wn0 + nf * 8 + gr];
                b[1] = Ws2[stage * 2112 + (kq + 4) * 264 + wn0 + nf * 8 + gr];
                mma16(acc[0][nf], a[0], b);
                mma16(acc[1][nf], a[1], b);
            }
        }
        if (has_next) stsAW(stage ^ 1);
        stage ^= 1;
    }

    // stash Eh tile (fp16) into ebuf: half2 col index = wn*32 + nf*4 + kq
#pragma unroll
    for (int s = 0; s < 2; s++)
#pragma unroll
    for (int half = 0; half < 2; half++) {
        int r = wm0 + s * 16 + gr + half * 8;
#pragma unroll
        for (int nf = 0; nf < 8; nf++) {
            ebuf[r * EBS + wn * 32 + nf * 4 + kq] =
                pack_h2(acc[s][nf][half * 2 + 0], acc[s][nf][half * 2 + 1]);
        }
    }
    __syncthreads();

    // ---- edge phase: warp w handles edges w*8 .. w*8+7; ce overwrites ebuf ----
    {
        const int c0 = lane * 4;
        const int h = lane >> 2;
        const int dbase = (lane & 3) * 4;
        float aw[4];
#pragma unroll
        for (int i = 0; i < 4; i++) aw[i] = Aw[(dbase + i) * NH + h];

#pragma unroll
        for (int g = 0; g < 2; g++) {
            int dstA[4], srcA[4];
            uint2 qA[4], kA[4], vA[4];
#pragma unroll
            for (int i = 0; i < 4; i++) {
                int e = e0 + wid * 8 + g * 4 + i;
                dstA[i] = ei[e];
                srcA[i] = ei[EE + e];
            }
#pragma unroll
            for (int i = 0; i < 4; i++) {
                qA[i] = *(const uint2*)&g_Qh[(size_t)dstA[i] * HIDD + c0];
                kA[i] = *(const uint2*)&g_Kh[(size_t)srcA[i] * HIDD + c0];
                vA[i] = *(const uint2*)&g_Vh[(size_t)srcA[i] * HIDD + c0];
            }
#pragma unroll
            for (int i = 0; i < 4; i++) {
                int r = wid * 8 + g * 4 + i;
                uint2 ewu = *(const uint2*)&ebuf[r * EBS + lane * 2];
                uint2 ebu = *(const uint2*)&ebuf[r * EBS + 64 + lane * 2];
                float2 ew01 = __half22float2(*(__half2*)&ewu.x);
                float2 ew23 = __half22float2(*(__half2*)&ewu.y);
                float2 eb01 = __half22float2(*(__half2*)&ebu.x);
                float2 eb23 = __half22float2(*(__half2*)&ebu.y);
                float2 q01 = __half22float2(*(__half2*)&qA[i].x);
                float2 q23 = __half22float2(*(__half2*)&qA[i].y);
                float2 k01 = __half22float2(*(__half2*)&kA[i].x);
                float2 k23 = __half22float2(*(__half2*)&kA[i].y);
                float2 v01 = __half22float2(*(__half2*)&vA[i].x);
                float2 v23 = __half22float2(*(__half2*)&vA[i].y);
                float ewf[4] = {ew01.x, ew01.y, ew23.x, ew23.y};
                float ebf[4] = {eb01.x, eb01.y, eb23.x, eb23.y};
                float qf[4] = {q01.x, q01.y, q23.x, q23.y};
                float kf[4] = {k01.x, k01.y, k23.x, k23.y};
                float vf[4] = {v01.x, v01.y, v23.x, v23.y};

                float ce[4];
                float part = 0.f;
#pragma unroll
                for (int j = 0; j < 4; j++) {
                    float m = qf[j] + kf[j];
                    float cc = m * ewf[j];
                    float ss = sqrtf(fabsf(cc));
                    ss = (cc >= 0.f) ? ss : -ss;      // signed sqrt
                    ce[j] = fmaxf(ss + ebf[j], 0.f);
                    part += ce[j] * aw[j];
                }
                // ce (fp16) replaces the Ew slots: half2 cols lane*2, lane*2+1
                uint2 cu;
                cu.x = pack_h2(ce[0], ce[1]);
                cu.y = pack_h2(ce[2], ce[3]);
                *(uint2*)&ebuf[r * EBS + lane * 2] = cu;

                part += __shfl_xor_sync(0xffffffffu, part, 1);
                part += __shfl_xor_sync(0xffffffffu, part, 2);
                float s = fminf(fmaxf(part, -5.f), 5.f);
                float p = __expf(s);

                if ((lane & 3) == 0) atomicAdd(&g_ssum[(size_t)dstA[i] * NH + h], p);
                float4 av = make_float4(vf[0] * p, vf[1] * p, vf[2] * p, vf[3] * p);
                float4 rv = make_float4(ce[0] * p, ce[1] * p, ce[2] * p, ce[3] * p);
                atomicAdd((float4*)&g_agg[(size_t)dstA[i] * HIDD + c0], av);
                atomicAdd((float4*)&g_row[(size_t)dstA[i] * HIDD + c0], rv);
            }
        }
    }

    // ---- GEMM2: out_e = LN1e(conn + ce @ Eo_w + Eo_b) ----
    // A = ce from ebuf (half2 cols 0..63); W = Eo_w via Ws2 double buffer.
    // Warp n-tile shrinks to 32 cols (wn quarter of 128).
    float acc2[2][4][4];
#pragma unroll
    for (int s = 0; s < 2; s++)
#pragma unroll
        for (int i = 0; i < 4; i++) { acc2[s][i][0] = acc2[s][i][1] = acc2[s][i][2] = acc2[s][i][3] = 0.f; }

    const int wj = t >> 5;             // 0..7 : k-row pair
    const int wcol = (t & 31) * 4;     // 0..124
    float4 eRa, eRb;
    auto loadW2 = [&](int ko) {
        eRa = *(const float4*)&Eo_w[(size_t)(ko + 2 * wj) * 128 + wcol];
        eRb = *(const float4*)&Eo_w[(size_t)(ko + 2 * wj + 1) * 128 + wcol];
    };
    auto stsW2 = [&](int st) {
        uint4 wv;
        wv.x = pack_h2(eRa.x, eRb.x); wv.y = pack_h2(eRa.y, eRb.y);
        wv.z = pack_h2(eRa.z, eRb.z); wv.w = pack_h2(eRa.w, eRb.w);
        *(uint4*)&Ws2[st * 2112 + wj * 264 + wcol] = wv;
    };

    loadW2(0); stsW2(0);
    int st2 = 0;
    for (int kt = 0; kt < 128; kt += 16) {
        const bool has_next = (kt + 16 < 128);
        if (has_next) loadW2(kt + 16);
        __syncthreads();   // 1st iter: edge-phase ce + W chunk0 visible
        {
            const int kt2 = kt >> 1;
            uint32_t a[2][4];
#pragma unroll
            for (int s = 0; s < 2; s++) {
                int mb = wm0 + s * 16;
                a[s][0] = ebuf[(mb + gr) * EBS + kt2 + kq];
                a[s][1] = ebuf[(mb + 8 + gr) * EBS + kt2 + kq];
                a[s][2] = ebuf[(mb + gr) * EBS + kt2 + kq + 4];
                a[s][3] = ebuf[(mb + 8 + gr) * EBS + kt2 + kq + 4];
            }
#pragma unroll
            for (int nf = 0; nf < 4; nf++) {
                uint32_t b[2];
                b[0] = Ws2[st2 * 2112 + kq * 264 + wn * 32 + nf * 8 + gr];
                b[1] = Ws2[st2 * 2112 + (kq + 4) * 264 + wn * 32 + nf * 8 + gr];
                mma16(acc2[0][nf], a[0], b);
                mma16(acc2[1][nf], a[1], b);
            }
        }
        if (has_next) stsW2(st2 ^ 1);
        st2 ^= 1;
    }

    // LN1e epilogue: row spans 4 n-warps -> partials via part2
    float v2[2][2][8];
#pragma unroll
    for (int s = 0; s < 2; s++)
#pragma unroll
    for (int half = 0; half < 2; half++) {
        int r = wm0 + s * 16 + gr + half * 8;
        int e = e0 + r;
        float sm = 0.f, s2sum = 0.f;
#pragma unroll
        for (int nf = 0; nf < 4; nf++) {
            int c = wn * 32 + nf * 8 + 2 * kq;
            float2 rr = *(const float2*)&conn[(size_t)e * 128 + c];
            float x0 = acc2[s][nf][half * 2 + 0] + Eo_b[c] + rr.x;
            float x1 = acc2[s][nf][half * 2 + 1] + Eo_b[c + 1] + rr.y;
            v2[s][half][2 * nf] = x0; v2[s][half][2 * nf + 1] = x1;
            sm += x0 + x1;
            s2sum += x0 * x0 + x1 * x1;
        }
#pragma unroll
        for (int off = 1; off < 4; off <<= 1) {
            sm += __shfl_xor_sync(0xffffffffu, sm, off);
            s2sum += __shfl_xor_sync(0xffffffffu, s2sum, off);
        }
        if (kq == 0) {
            part2[r * 8 + wn * 2 + 0] = sm;
            part2[r * 8 + wn * 2 + 1] = s2sum;
        }
    }
    __syncthreads();
#pragma unroll
    for (int s = 0; s < 2; s++)
#pragma unroll
    for (int half = 0; half < 2; half++) {
        int r = wm0 + s * 16 + gr + half * 8;
        int e = e0 + r;
        float sm = part2[r * 8 + 0] + part2[r * 8 + 2] + part2[r * 8 + 4] + part2[r * 8 + 6];
        float s2v = part2[r * 8 + 1] + part2[r * 8 + 3] + part2[r * 8 + 5] + part2[r * 8 + 7];
        float mean = sm * (1.f / 128.f);
        float var = s2v * (1.f / 128.f) - mean * mean;
        float rstd = rsqrtf(var + 1e-5f);
#pragma unroll
        for (int nf = 0; nf < 4; nf++) {
            int c = wn * 32 + nf * 8 + 2 * kq;
            float o0 = (v2[s][half][2 * nf] - mean) * rstd * ln1e_g[c] + ln1e_b[c];
            float o1 = (v2[s][half][2 * nf + 1] - mean) * rstd * ln1e_g[c + 1] + ln1e_b[c + 1];
            *(float2*)&out_e[(size_t)e * 128 + c] = make_float2(o0, o1);
        }
    }
}

// ---------------- node pass: normalize, rowV = row @ Bw, deg scaling ----------------
__global__ void __launch_bounds__(256) node_kernel(const float* __restrict__ Bw,
                                                   const float* __restrict__ deg_coef,
                                                   const float* __restrict__ log_deg)
{
    __shared__ float rbuf[8][HIDD];
    int n = (int)((blockIdx.x * (size_t)blockDim.x + threadIdx.x) >> 5);
    int wl = (threadIdx.x >> 5) & 7;
    int l = threadIdx.x & 31;
    if (n >= NN) return;
    int h = l >> 2;
    int c0 = l * 4;

    float rs = 1.f / (g_ssum[(size_t)n * NH + h] + 1e-16f);
    float4 a = *(const float4*)&g_agg[(size_t)n * HIDD + c0];
    float4 r = *(const float4*)&g_row[(size_t)n * HIDD + c0];
    a.x *= rs; a.y *= rs; a.z *= rs; a.w *= rs;
    r.x *= rs; r.y *= rs; r.z *= rs; r.w *= rs;
    *(float4*)&rbuf[wl][c0] = r;
    __syncwarp();

    uint2 qu = *(const uint2*)&g_Qh[(size_t)n * HIDD + c0];
    float2 q01 = __half22float2(*(__half2*)&qu.x);
    float2 q23 = __half22float2(*(__half2*)&qu.y);
    float qf[4] = {q01.x, q01.y, q23.x, q23.y};
    const float* af = (const float*)&a;
    float ld = log_deg[n];

    float out[4];
#pragma unroll
    for (int i = 0; i < 4; i++) {
        int c = c0 + i;
        float rv = 0.f;
#pragma unroll
        for (int d = 0; d < DDIM; d++)
            rv = fmaf(rbuf[wl][h * DDIM + d], __ldg(&Bw[d * HIDD + c]), rv);
        float ha = qf[i] + af[i] + rv;
        out[i] = ha * (deg_coef[2 * c] + ld * deg_coef[2 * c + 1]);
    }
    *(float4*)&g_hpre[(size_t)n * HIDD + c0] = make_float4(out[0], out[1], out[2], out[3]);
}

// ---------------- launch ----------------
extern "C" void kernel_launch(void* const* d_in, const int* in_sizes, int n_in,
                              void* d_out, int out_size)
{
    const float* x        = (const float*)d_in[0];
    const float* conn     = (const float*)d_in[1];
    const float* log_deg  = (const float*)d_in[2];
    const int*   ei       = (const int*)d_in[3];
    const float* WQ       = (const float*)d_in[4];
    const float* WK       = (const float*)d_in[5];
    const float* WV       = (const float*)d_in[6];
    const float* WE       = (const float*)d_in[7];
    const float* Aw       = (const float*)d_in[8];
    const float* Bw       = (const float*)d_in[9];
    const float* Ho_w     = (const float*)d_in[10];
    const float* Ho_b     = (const float*)d_in[11];
    const float* Eo_w     = (const float*)d_in[12];
    const float* Eo_b     = (const float*)d_in[13];
    const float* deg_coef = (const float*)d_in[14];
    const float* ln1h_g   = (const float*)d_in[15];
    const float* ln1h_b   = (const float*)d_in[16];
    const float* ln1e_g   = (const float*)d_in[17];
    const float* ln1e_b   = (const float*)d_in[18];
    const float* ln2h_g   = (const float*)d_in[19];
    const float* ln2h_b   = (const float*)d_in[20];
    const float* W1       = (const float*)d_in[21];
    const float* b1       = (const float*)d_in[22];
    const float* W2       = (const float*)d_in[23];
    const float* b2       = (const float*)d_in[24];

    float* out_h = (float*)d_out;
    float* out_e = out_h + (size_t)NN * HIDD;

    float *ssum, *agg, *row, *hpre, *h1, *mlp;
    __half *Qh, *Kh, *Vh;
    cudaGetSymbolAddress((void**)&Qh, g_Qh);
    cudaGetSymbolAddress((void**)&Kh, g_Kh);
    cudaGetSymbolAddress((void**)&Vh, g_Vh);
    cudaGetSymbolAddress((void**)&ssum, g_ssum);
    cudaGetSymbolAddress((void**)&agg, g_agg);
    cudaGetSymbolAddress((void**)&row, g_row);
    cudaGetSymbolAddress((void**)&hpre, g_hpre);
    cudaGetSymbolAddress((void**)&h1, g_h1);
    cudaGetSymbolAddress((void**)&mlp, g_mlp);

    cudaFuncSetAttribute(eh_edge_gemm, cudaFuncAttributeMaxDynamicSharedMemorySize, FUS_SMEM);

    const int gN = (NN + 127) / 128;   // 391

    cudaMemsetAsync(ssum, 0, (size_t)NN * NH * sizeof(float), 0);
    cudaMemsetAsync(agg, 0, (size_t)NN * HIDD * sizeof(float), 0);
    cudaMemsetAsync(row, 0, (size_t)NN * HIDD * sizeof(float), 0);

    // Qh, Kh, Vh (fp32 A, fp16 C)
    tgemm<128, 0, false, true, false><<<dim3(gN, 1), 256>>>(x, WQ, 128, nullptr, nullptr, nullptr, nullptr, Qh, 128, NN);
    tgemm<128, 0, false, true, false><<<dim3(gN, 1), 256>>>(x, WK, 128, nullptr, nullptr, nullptr, nullptr, Kh, 128, NN);
    tgemm<128, 0, false, true, false><<<dim3(gN, 1), 256>>>(x, WV, 128, nullptr, nullptr, nullptr, nullptr, Vh, 128, NN);

    // fused: Eh GEMM + edge pass + Eo GEMM + LN1e (ce/Eh never hit gmem)
    eh_edge_gemm<<<EE / 64, 256, FUS_SMEM>>>(conn, WE, ei, Aw, Eo_w, Eo_b, ln1e_g, ln1e_b, out_e);

    // node pass -> h_pre
    node_kernel<<<(NN * 32 + 255) / 256, 256>>>(Bw, deg_coef, log_deg);

    // h1 = LN1h(x + hpre @ Ho_w + Ho_b)
    tgemm<128, 2, false, false, false><<<dim3(gN, 1), 256>>>(hpre, Ho_w, 128, Ho_b, x, ln1h_g, ln1h_b, h1, 128, NN);
    // mlp = relu(h1 @ W1 + b1); grid swapped for h1 L2 reuse
    tgemm<128, 1, false, false, true><<<dim3(2, gN), 256>>>(h1, W1, 256, b1, nullptr, nullptr, nullptr, mlp, 256, NN);
    // out_h = LN2h(h1 + mlp @ W2 + b2)
    tgemm<256, 2, false, false, false><<<dim3(gN, 1), 256>>>(mlp, W2, 128, b2, h1, ln2h_g, ln2h_b, out_h, 128, NN);
}

// round 17
// speedup vs baseline: 2.2294x; 1.0079x over previous
#include <cuda_runtime.h>
#include <cuda_fp16.h>
#include <cstdint>

#define NN 50000
#define EE 600000
#define HIDD 128
#define NH 8
#define DDIM 16

// ---------------- scratch (device globals; no allocation allowed) ----------------
__device__ __half g_Qh[(size_t)NN * HIDD];
__device__ __half g_Kh[(size_t)NN * HIDD];
__device__ __half g_Vh[(size_t)NN * HIDD];
__device__ float  g_ssum[(size_t)NN * NH];
__device__ float  g_agg[(size_t)NN * HIDD];
__device__ float  g_row[(size_t)NN * HIDD];
__device__ float  g_hpre[(size_t)NN * HIDD];
__device__ float  g_h1[(size_t)NN * HIDD];
__device__ float  g_mlp[(size_t)NN * 256];

__device__ __forceinline__ void mma16(float* c, const uint32_t* a, const uint32_t* b) {
    asm volatile(
        "mma.sync.aligned.m16n8k16.row.col.f32.f16.f16.f32 "
        "{%0,%1,%2,%3},{%4,%5,%6,%7},{%8,%9},{%0,%1,%2,%3};"
        : "+f"(c[0]), "+f"(c[1]), "+f"(c[2]), "+f"(c[3])
        : "r"(a[0]), "r"(a[1]), "r"(a[2]), "r"(a[3]), "r"(b[0]), "r"(b[1]));
}

__device__ __forceinline__ uint32_t pack_h2(float lo, float hi) {
    __half2 h = __floats2half2_rn(lo, hi);   // lo -> low half
    return *(uint32_t*)&h;
}

// ---------------- FP16 tensor-core GEMM (R14 winner, unchanged core) ------------
#define SMS 136
template <int KD, int EPI, bool AHALF, bool CHALF, bool SWAPG>
__global__ void __launch_bounds__(256, 2) tgemm(
    const void* __restrict__ Av, const float* __restrict__ W, int ldw,
    const float* __restrict__ bias, const float* __restrict__ resid,
    const float* __restrict__ lng, const float* __restrict__ lnb,
    void* __restrict__ Cv, int ldc, int M)
{
    const float*  Af = (const float*)Av;
    const __half* Ah = (const __half*)Av;
    float*  Cf = (float*)Cv;
    __half* Ch = (__half*)Cv;

    __shared__ uint32_t As2[2][8][SMS];
    __shared__ uint32_t Ws2[2][8][SMS];
    __shared__ float part[128][2][2];

    const int t = threadIdx.x;
    const int lane = t & 31;
    const int wid = t >> 5;
    const int wn = wid & 1;
    const int wm = wid >> 1;
    const int bxm = SWAPG ? blockIdx.y : blockIdx.x;
    const int bxn = SWAPG ? blockIdx.x : blockIdx.y;
    const int m0b = bxm * 128;
    const int n0 = bxn * 128;
    const int wm0 = wm * 32;
    const int wn0 = wn * 64;
    const int gr = lane >> 2;
    const int kq = lane & 3;

    float acc[2][8][4];
#pragma unroll
    for (int s = 0; s < 2; s++)
#pragma unroll
        for (int i = 0; i < 8; i++) { acc[s][i][0] = acc[s][i][1] = acc[s][i][2] = acc[s][i][3] = 0.f; }

    const int arow = t >> 2;
    const int acol = (t & 3) * 4;
    const int ak2 = acol >> 1;
    const int wj = t >> 5;
    const int wcol = (t & 31) * 4;

    float4 aRf[2]; uint2 aRh[2];
    float4 wRa, wRb;

    auto loadA = [&](int ko) {
#pragma unroll
        for (int p = 0; p < 2; p++) {
            int row = m0b + arow + p * 64;
            if (AHALF) {
                aRh[p] = make_uint2(0u, 0u);
                if (row < M) aRh[p] = *(const uint2*)&Ah[(size_t)row * KD + ko + acol];
            } else {
                aRf[p] = make_float4(0.f, 0.f, 0.f, 0.f);
                if (row < M) aRf[p] = *(const float4*)&Af[(size_t)row * KD + ko + acol];
            }
        }
    };
    auto loadW = [&](int ko) {
        wRa = *(const float4*)&W[(size_t)(ko + 2 * wj) * ldw + n0 + wcol];
        wRb = *(const float4*)&W[(size_t)(ko + 2 * wj + 1) * ldw + n0 + wcol];
    };
    auto stsAW = [&](int st) {
#pragma unroll
        for (int p = 0; p < 2; p++) {
            int m = arow + p * 64;
            if (AHALF) {
                As2[st][ak2 + 0][m] = aRh[p].x;
                As2[st][ak2 + 1][m] = aRh[p].y;
            } else {
                As2[st][ak2 + 0][m] = pack_h2(aRf[p].x, aRf[p].y);
                As2[st][ak2 + 1][m] = pack_h2(aRf[p].z, aRf[p].w);
            }
        }
        uint4 wv;
        wv.x = pack_h2(wRa.x, wRb.x); wv.y = pack_h2(wRa.y, wRb.y);
        wv.z = pack_h2(wRa.z, wRb.z); wv.w = pack_h2(wRa.w, wRb.w);
        *(uint4*)&Ws2[st][wj][wcol] = wv;
    };

    loadA(0); loadW(0); stsAW(0);

    int stage = 0;
    for (int kt = 0; kt < KD; kt += 16) {
        const bool has_next = (kt + 16 < KD);
        if (has_next) { loadA(kt + 16); loadW(kt + 16); }
        __syncthreads();
        {
            uint32_t a[2][4];
#pragma unroll
            for (int s = 0; s < 2; s++) {
                int mb = wm0 + s * 16;
                a[s][0] = As2[stage][kq][mb + gr];
                a[s][1] = As2[stage][kq][mb + 8 + gr];
                a[s][2] = As2[stage][kq + 4][mb + gr];
                a[s][3] = As2[stage][kq + 4][mb + 8 + gr];
            }
#pragma unroll
            for (int nf = 0; nf < 8; nf++) {
                uint32_t b[2];
                b[0] = Ws2[stage][kq][wn0 + nf * 8 + gr];
                b[1] = Ws2[stage][kq + 4][wn0 + nf * 8 + gr];
                mma16(acc[0][nf], a[0], b);
                mma16(acc[1][nf], a[1], b);
            }
        }
        if (has_next) stsAW(stage ^ 1);
        stage ^= 1;
    }

    if (EPI == 0 || EPI == 1) {
#pragma unroll
        for (int s = 0; s < 2; s++)
#pragma unroll
        for (int half = 0; half < 2; half++) {
            int r = m0b + wm0 + s * 16 + gr + half * 8;
            if (r >= M) continue;
#pragma unroll
            for (int nf = 0; nf < 8; nf++) {
                int c = n0 + wn0 + nf * 8 + 2 * kq;
                float v0 = acc[s][nf][half * 2 + 0];
                float v1 = acc[s][nf][half * 2 + 1];
                if (bias) { v0 += bias[c]; v1 += bias[c + 1]; }
                if (EPI == 1) { v0 = fmaxf(v0, 0.f); v1 = fmaxf(v1, 0.f); }
                if (CHALF) {
                    *(uint32_t*)&Ch[(size_t)r * ldc + c] = pack_h2(v0, v1);
                } else {
                    *(float2*)&Cf[(size_t)r * ldc + c] = make_float2(v0, v1);
                }
            }
        }
    } else {
        float v[2][2][16];
#pragma unroll
        for (int s = 0; s < 2; s++)
#pragma unroll
        for (int half = 0; half < 2; half++) {
            int r = m0b + wm0 + s * 16 + gr + half * 8;
            bool ok = (r < M);
            float sm = 0.f, s2 = 0.f;
#pragma unroll
            for (int nf = 0; nf < 8; nf++) {
                int c = wn0 + nf * 8 + 2 * kq;
                float x0 = acc[s][nf][half * 2 + 0] + bias[c];
                float x1 = acc[s][nf][half * 2 + 1] + bias[c + 1];
                if (ok) {
                    float2 rr = *(const float2*)&resid[(size_t)r * 128 + c];
                    x0 += rr.x; x1 += rr.y;
                }
                v[s][half][2 * nf] = x0; v[s][half][2 * nf + 1] = x1;
                sm += x0 + x1;
                s2 += x0 * x0 + x1 * x1;
            }
#pragma unroll
            for (int off = 1; off < 4; off <<= 1) {
                sm += __shfl_xor_sync(0xffffffffu, sm, off);
                s2 += __shfl_xor_sync(0xffffffffu, s2, off);
            }
            if (kq == 0) {
                int lr = wm0 + s * 16 + gr + half * 8;
                part[lr][wn][0] = sm;
                part[lr][wn][1] = s2;
            }
        }
        __syncthreads();
#pragma unroll
        for (int s = 0; s < 2; s++)
#pragma unroll
        for (int half = 0; half < 2; half++) {
            int lr = wm0 + s * 16 + gr + half * 8;
            int r = m0b + lr;
            if (r >= M) continue;
            float sm = part[lr][0][0] + part[lr][1][0];
            float s2 = part[lr][0][1] + part[lr][1][1];
            float mean = sm * (1.f / 128.f);
            float var = s2 * (1.f / 128.f) - mean * mean;
            float rstd = rsqrtf(var + 1e-5f);
#pragma unroll
            for (int nf = 0; nf < 8; nf++) {
                int c = wn0 + nf * 8 + 2 * kq;
                float o0 = (v[s][half][2 * nf] - mean) * rstd * lng[c] + lnb[c];
                float o1 = (v[s][half][2 * nf + 1] - mean) * rstd * lng[c + 1] + lnb[c + 1];
                *(float2*)&Cf[(size_t)r * 128 + c] = make_float2(o0, o1);
            }
        }
    }
}

// ---------------- fused Eh-GEMM + edge pass + Eo-GEMM + LN1e --------------------
// CTA = 64 edges.  Phase 1: Eh = conn@WE (256 cols) -> ebuf (fp16).
// Phase 2: edge math in-block (ce overwrites ebuf; atomics); ei prefetched at
//          kernel entry (lanes 0-7, shfl-broadcast) so the index load is hidden.
// Phase 3: out_e = LN1e(conn + ce@Eo_w + Eo_b).  Eo_w preloaded ONCE into its
//          own smem region (LDGs issued right after phase-1 mainloop, overlap
//          the ebuf stash + edge phase) -> GEMM2 runs with ZERO barriers.
// smem (uint32): As2 2*8*76 | Ws2 2*8*264 | ebuf 64*132 | EOW 64*136 | part2 512f
#define ASZ (2 * 8 * 76)
#define WSZ (2 * 8 * 264)
#define EBS 132
#define EOS 136
#define FUS_SMEM ((ASZ + WSZ + 64 * EBS + 64 * EOS + 64 * 8) * 4)

__global__ void __launch_bounds__(256, 2) eh_edge_gemm(
    const float* __restrict__ conn, const float* __restrict__ WE,
    const int* __restrict__ ei, const float* __restrict__ Aw,
    const float* __restrict__ Eo_w, const float* __restrict__ Eo_b,
    const float* __restrict__ ln1e_g, const float* __restrict__ ln1e_b,
    float* __restrict__ out_e)
{
    extern __shared__ uint32_t dsm[];
    uint32_t* As2 = dsm;                       // [st][k2][m] : st*608 + k2*76 + m
    uint32_t* Ws2 = dsm + ASZ;                 // [st][k2][n] : st*2112 + k2*264 + n
    uint32_t* ebuf = dsm + ASZ + WSZ;          // [r][c2]     : r*132 + c2
    uint32_t* eow = dsm + ASZ + WSZ + 64 * EBS;        // [k2][c] : k2*136 + c
    float* part2 = (float*)(dsm + ASZ + WSZ + 64 * EBS + 64 * EOS);

    const int t = threadIdx.x;
    const int lane = t & 31;
    const int wid = t >> 5;            // 0..7
    const int wn = wid & 3;            // n quarter
    const int wm = wid >> 2;           // m half (32 rows)
    const int e0 = blockIdx.x * 64;    // EE % 64 == 0
    const int wm0 = wm * 32;
    const int wn0 = wn * 64;
    const int gr = lane >> 2;
    const int kq = lane & 3;

    // prefetch this warp's 8 edge indices (lanes 0..7); consumed via shfl later
    int myDst = 0, mySrc = 0;
    if (lane < 8) {
        int e = e0 + wid * 8 + lane;
        myDst = ei[e];
        mySrc = ei[EE + e];
    }

    float acc[2][8][4];
#pragma unroll
    for (int s = 0; s < 2; s++)
#pragma unroll
        for (int i = 0; i < 8; i++) { acc[s][i][0] = acc[s][i][1] = acc[s][i][2] = acc[s][i][3] = 0.f; }

    const int arow = t >> 2;           // 0..63
    const int acol = (t & 3) * 4;
    const int ak2 = acol >> 1;
    const int wp = t >> 6;             // 0..3
    const int wc4 = (t & 63) * 4;      // 0..252

    float4 aRf;
    float4 wRa0, wRb0, wRa1, wRb1;

    auto loadA = [&](int ko) {
        aRf = *(const float4*)&conn[(size_t)(e0 + arow) * 128 + ko + acol];
    };
    auto loadW = [&](int ko) {
        wRa0 = *(const float4*)&WE[(size_t)(ko + 2 * wp) * 256 + wc4];
        wRb0 = *(const float4*)&WE[(size_t)(ko + 2 * wp + 1) * 256 + wc4];
        wRa1 = *(const float4*)&WE[(size_t)(ko + 2 * wp + 8) * 256 + wc4];
        wRb1 = *(const float4*)&WE[(size_t)(ko + 2 * wp + 9) * 256 + wc4];
    };
    auto stsAW = [&](int st) {
        As2[st * 608 + (ak2 + 0) * 76 + arow] = pack_h2(aRf.x, aRf.y);
        As2[st * 608 + (ak2 + 1) * 76 + arow] = pack_h2(aRf.z, aRf.w);
        uint4 wv;
        wv.x = pack_h2(wRa0.x, wRb0.x); wv.y = pack_h2(wRa0.y, wRb0.y);
        wv.z = pack_h2(wRa0.z, wRb0.z); wv.w = pack_h2(wRa0.w, wRb0.w);
        *(uint4*)&Ws2[st * 2112 + wp * 264 + wc4] = wv;
        wv.x = pack_h2(wRa1.x, wRb1.x); wv.y = pack_h2(wRa1.y, wRb1.y);
        wv.z = pack_h2(wRa1.z, wRb1.z); wv.w = pack_h2(wRa1.w, wRb1.w);
        *(uint4*)&Ws2[st * 2112 + (wp + 4) * 264 + wc4] = wv;
    };

    loadA(0); loadW(0); stsAW(0);

    int stage = 0;
    for (int kt = 0; kt < 128; kt += 16) {
        const bool has_next = (kt + 16 < 128);
        if (has_next) { loadA(kt + 16); loadW(kt + 16); }
        __syncthreads();
        {
            uint32_t a[2][4];
#pragma unroll
            for (int s = 0; s < 2; s++) {
                int mb = wm0 + s * 16;
                a[s][0] = As2[stage * 608 + kq * 76 + mb + gr];
                a[s][1] = As2[stage * 608 + kq * 76 + mb + 8 + gr];
                a[s][2] = As2[stage * 608 + (kq + 4) * 76 + mb + gr];
                a[s][3] = As2[stage * 608 + (kq + 4) * 76 + mb + 8 + gr];
            }
#pragma unroll
            for (int nf = 0; nf < 8; nf++) {
                uint32_t b[2];
                b[0] = Ws2[stage * 2112 + kq * 264 + wn0 + nf * 8 + gr];
                b[1] = Ws2[stage * 2112 + (kq + 4) * 264 + wn0 + nf * 8 + gr];
                mma16(acc[0][nf], a[0], b);
                mma16(acc[1][nf], a[1], b);
            }
        }
        if (has_next) stsAW(stage ^ 1);
        stage ^= 1;
    }

    // ---- preload Eo_w into EOW (LDGs overlap ebuf stash + edge phase) ----
    {
        const int wj2 = t >> 5;            // 0..7
        const int wc2 = (t & 31) * 4;      // 0..124
#pragma unroll
        for (int rp = 0; rp < 8; rp++) {
            int k2 = wj2 + 8 * rp;         // 0..63
            float4 ra = *(const float4*)&Eo_w[(size_t)(2 * k2) * 128 + wc2];
            float4 rb = *(const float4*)&Eo_w[(size_t)(2 * k2 + 1) * 128 + wc2];
            uint4 wv;
            wv.x = pack_h2(ra.x, rb.x); wv.y = pack_h2(ra.y, rb.y);
            wv.z = pack_h2(ra.z, rb.z); wv.w = pack_h2(ra.w, rb.w);
            *(uint4*)&eow[k2 * EOS + wc2] = wv;
        }
    }

    // stash Eh tile (fp16) into ebuf: half2 col index = wn*32 + nf*4 + kq
#pragma unroll
    for (int s = 0; s < 2; s++)
#pragma unroll
    for (int half = 0; half < 2; half++) {
        int r = wm0 + s * 16 + gr + half * 8;
#pragma unroll
        for (int nf = 0; nf < 8; nf++) {
            ebuf[r * EBS + wn * 32 + nf * 4 + kq] =
                pack_h2(acc[s][nf][half * 2 + 0], acc[s][nf][half * 2 + 1]);
        }
    }
    __syncthreads();

    // ---- edge phase: warp w handles edges w*8 .. w*8+7; ce overwrites ebuf ----
    {
        const int c0 = lane * 4;
        const int h = lane >> 2;
        const int dbase = (lane & 3) * 4;
        float aw[4];
#pragma unroll
        for (int i = 0; i < 4; i++) aw[i] = Aw[(dbase + i) * NH + h];

#pragma unroll
        for (int g = 0; g < 2; g++) {
            int dstA[4], srcA[4];
            uint2 qA[4], kA[4], vA[4];
#pragma unroll
            for (int i = 0; i < 4; i++) {
                dstA[i] = __shfl_sync(0xffffffffu, myDst, g * 4 + i);
                srcA[i] = __shfl_sync(0xffffffffu, mySrc, g * 4 + i);
            }
#pragma unroll
            for (int i = 0; i < 4; i++) {
                qA[i] = *(const uint2*)&g_Qh[(size_t)dstA[i] * HIDD + c0];
                kA[i] = *(const uint2*)&g_Kh[(size_t)srcA[i] * HIDD + c0];
                vA[i] = *(const uint2*)&g_Vh[(size_t)srcA[i] * HIDD + c0];
            }
#pragma unroll
            for (int i = 0; i < 4; i++) {
                int r = wid * 8 + g * 4 + i;
                uint2 ewu = *(const uint2*)&ebuf[r * EBS + lane * 2];
                uint2 ebu = *(const uint2*)&ebuf[r * EBS + 64 + lane * 2];
                float2 ew01 = __half22float2(*(__half2*)&ewu.x);
                float2 ew23 = __half22float2(*(__half2*)&ewu.y);
                float2 eb01 = __half22float2(*(__half2*)&ebu.x);
                float2 eb23 = __half22float2(*(__half2*)&ebu.y);
                float2 q01 = __half22float2(*(__half2*)&qA[i].x);
                float2 q23 = __half22float2(*(__half2*)&qA[i].y);
                float2 k01 = __half22float2(*(__half2*)&kA[i].x);
                float2 k23 = __half22float2(*(__half2*)&kA[i].y);
                float2 v01 = __half22float2(*(__half2*)&vA[i].x);
                float2 v23 = __half22float2(*(__half2*)&vA[i].y);
                float ewf[4] = {ew01.x, ew01.y, ew23.x, ew23.y};
                float ebf[4] = {eb01.x, eb01.y, eb23.x, eb23.y};
                float qf[4] = {q01.x, q01.y, q23.x, q23.y};
                float kf[4] = {k01.x, k01.y, k23.x, k23.y};
                float vf[4] = {v01.x, v01.y, v23.x, v23.y};

                float ce[4];
                float part = 0.f;
#pragma unroll
                for (int j = 0; j < 4; j++) {
                    float m = qf[j] + kf[j];
                    float cc = m * ewf[j];
                    float ss = sqrtf(fabsf(cc));
                    ss = (cc >= 0.f) ? ss : -ss;      // signed sqrt
                    ce[j] = fmaxf(ss + ebf[j], 0.f);
                    part += ce[j] * aw[j];
                }
                uint2 cu;
                cu.x = pack_h2(ce[0], ce[1]);
                cu.y = pack_h2(ce[2], ce[3]);
                *(uint2*)&ebuf[r * EBS + lane * 2] = cu;

                part += __shfl_xor_sync(0xffffffffu, part, 1);
                part += __shfl_xor_sync(0xffffffffu, part, 2);
                float s = fminf(fmaxf(part, -5.f), 5.f);
                float p = __expf(s);

                if ((lane & 3) == 0) atomicAdd(&g_ssum[(size_t)dstA[i] * NH + h], p);
                float4 av = make_float4(vf[0] * p, vf[1] * p, vf[2] * p, vf[3] * p);
                float4 rv = make_float4(ce[0] * p, ce[1] * p, ce[2] * p, ce[3] * p);
                atomicAdd((float4*)&g_agg[(size_t)dstA[i] * HIDD + c0], av);
                atomicAdd((float4*)&g_row[(size_t)dstA[i] * HIDD + c0], rv);
            }
        }
    }
    __syncthreads();   // ce + EOW visible to all warps

    // ---- GEMM2 (barrier-free): out_e = LN1e(conn + ce @ Eo_w + Eo_b) ----
    float acc2[2][4][4];
#pragma unroll
    for (int s = 0; s < 2; s++)
#pragma unroll
        for (int i = 0; i < 4; i++) { acc2[s][i][0] = acc2[s][i][1] = acc2[s][i][2] = acc2[s][i][3] = 0.f; }

#pragma unroll
    for (int kt2 = 0; kt2 < 64; kt2 += 8) {
        uint32_t a[2][4];
#pragma unroll
        for (int s = 0; s < 2; s++) {
            int mb = wm0 + s * 16;
            a[s][0] = ebuf[(mb + gr) * EBS + kt2 + kq];
            a[s][1] = ebuf[(mb + 8 + gr) * EBS + kt2 + kq];
            a[s][2] = ebuf[(mb + gr) * EBS + kt2 + kq + 4];
            a[s][3] = ebuf[(mb + 8 + gr) * EBS + kt2 + kq + 4];
        }
#pragma unroll
        for (int nf = 0; nf < 4; nf++) {
            uint32_t b[2];
            b[0] = eow[(kt2 + kq) * EOS + wn * 32 + nf * 8 + gr];
            b[1] = eow[(kt2 + kq + 4) * EOS + wn * 32 + nf * 8 + gr];
            mma16(acc2[0][nf], a[0], b);
            mma16(acc2[1][nf], a[1], b);
        }
    }

    // LN1e epilogue: row spans 4 n-warps -> partials via part2
    float v2[2][2][8];
#pragma unroll
    for (int s = 0; s < 2; s++)
#pragma unroll
    for (int half = 0; half < 2; half++) {
        int r = wm0 + s * 16 + gr + half * 8;
        int e = e0 + r;
        float sm = 0.f, s2sum = 0.f;
#pragma unroll
        for (int nf = 0; nf < 4; nf++) {
            int c = wn * 32 + nf * 8 + 2 * kq;
            float2 rr = *(const float2*)&conn[(size_t)e * 128 + c];
            float x0 = acc2[s][nf][half * 2 + 0] + Eo_b[c] + rr.x;
            float x1 = acc2[s][nf][half * 2 + 1] + Eo_b[c + 1] + rr.y;
            v2[s][half][2 * nf] = x0; v2[s][half][2 * nf + 1] = x1;
            sm += x0 + x1;
            s2sum += x0 * x0 + x1 * x1;
        }
#pragma unroll
        for (int off = 1; off < 4; off <<= 1) {
            sm += __shfl_xor_sync(0xffffffffu, sm, off);
            s2sum += __shfl_xor_sync(0xffffffffu, s2sum, off);
        }
        if (kq == 0) {
            part2[r * 8 + wn * 2 + 0] = sm;
            part2[r * 8 + wn * 2 + 1] = s2sum;
        }
    }
    __syncthreads();
#pragma unroll
    for (int s = 0; s < 2; s++)
#pragma unroll
    for (int half = 0; half < 2; half++) {
        int r = wm0 + s * 16 + gr + half * 8;
        int e = e0 + r;
        float sm = part2[r * 8 + 0] + part2[r * 8 + 2] + part2[r * 8 + 4] + part2[r * 8 + 6];
        float s2v = part2[r * 8 + 1] + part2[r * 8 + 3] + part2[r * 8 + 5] + part2[r * 8 + 7];
        float mean = sm * (1.f / 128.f);
        float var = s2v * (1.f / 128.f) - mean * mean;
        float rstd = rsqrtf(var + 1e-5f);
#pragma unroll
        for (int nf = 0; nf < 4; nf++) {
            int c = wn * 32 + nf * 8 + 2 * kq;
            float o0 = (v2[s][half][2 * nf] - mean) * rstd * ln1e_g[c] + ln1e_b[c];
            float o1 = (v2[s][half][2 * nf + 1] - mean) * rstd * ln1e_g[c + 1] + ln1e_b[c + 1];
            *(float2*)&out_e[(size_t)e * 128 + c] = make_float2(o0, o1);
        }
    }
}

// ---------------- node pass: normalize, rowV = row @ Bw, deg scaling ----------------
__global__ void __launch_bounds__(256) node_kernel(const float* __restrict__ Bw,
                                                   const float* __restrict__ deg_coef,
                                                   const float* __restrict__ log_deg)
{
    __shared__ float rbuf[8][HIDD];
    int n = (int)((blockIdx.x * (size_t)blockDim.x + threadIdx.x) >> 5);
    int wl = (threadIdx.x >> 5) & 7;
    int l = threadIdx.x & 31;
    if (n >= NN) return;
    int h = l >> 2;
    int c0 = l * 4;

    float rs = 1.f / (g_ssum[(size_t)n * NH + h] + 1e-16f);
    float4 a = *(const float4*)&g_agg[(size_t)n * HIDD + c0];
    float4 r = *(const float4*)&g_row[(size_t)n * HIDD + c0];
    a.x *= rs; a.y *= rs; a.z *= rs; a.w *= rs;
    r.x *= rs; r.y *= rs; r.z *= rs; r.w *= rs;
    *(float4*)&rbuf[wl][c0] = r;
    __syncwarp();

    uint2 qu = *(const uint2*)&g_Qh[(size_t)n * HIDD + c0];
    float2 q01 = __half22float2(*(__half2*)&qu.x);
    float2 q23 = __half22float2(*(__half2*)&qu.y);
    float qf[4] = {q01.x, q01.y, q23.x, q23.y};
    const float* af = (const float*)&a;
    float ld = log_deg[n];

    float out[4];
#pragma unroll
    for (int i = 0; i < 4; i++) {
        int c = c0 + i;
        float rv = 0.f;
#pragma unroll
        for (int d = 0; d < DDIM; d++)
            rv = fmaf(rbuf[wl][h * DDIM + d], __ldg(&Bw[d * HIDD + c]), rv);
        float ha = qf[i] + af[i] + rv;
        out[i] = ha * (deg_coef[2 * c] + ld * deg_coef[2 * c + 1]);
    }
    *(float4*)&g_hpre[(size_t)n * HIDD + c0] = make_float4(out[0], out[1], out[2], out[3]);
}

// ---------------- launch ----------------
extern "C" void kernel_launch(void* const* d_in, const int* in_sizes, int n_in,
                              void* d_out, int out_size)
{
    const float* x        = (const float*)d_in[0];
    const float* conn     = (const float*)d_in[1];
    const float* log_deg  = (const float*)d_in[2];
    const int*   ei       = (const int*)d_in[3];
    const float* WQ       = (const float*)d_in[4];
    const float* WK       = (const float*)d_in[5];
    const float* WV       = (const float*)d_in[6];
    const float* WE       = (const float*)d_in[7];
    const float* Aw       = (const float*)d_in[8];
    const float* Bw       = (const float*)d_in[9];
    const float* Ho_w     = (const float*)d_in[10];
    const float* Ho_b     = (const float*)d_in[11];
    const float* Eo_w     = (const float*)d_in[12];
    const float* Eo_b     = (const float*)d_in[13];
    const float* deg_coef = (const float*)d_in[14];
    const float* ln1h_g   = (const float*)d_in[15];
    const float* ln1h_b   = (const float*)d_in[16];
    const float* ln1e_g   = (const float*)d_in[17];
    const float* ln1e_b   = (const float*)d_in[18];
    const float* ln2h_g   = (const float*)d_in[19];
    const float* ln2h_b   = (const float*)d_in[20];
    const float* W1       = (const float*)d_in[21];
    const float* b1       = (const float*)d_in[22];
    const float* W2       = (const float*)d_in[23];
    const float* b2       = (const float*)d_in[24];

    float* out_h = (float*)d_out;
    float* out_e = out_h + (size_t)NN * HIDD;

    float *ssum, *agg, *row, *hpre, *h1, *mlp;
    __half *Qh, *Kh, *Vh;
    cudaGetSymbolAddress((void**)&Qh, g_Qh);
    cudaGetSymbolAddress((void**)&Kh, g_Kh);
    cudaGetSymbolAddress((void**)&Vh, g_Vh);
    cudaGetSymbolAddress((void**)&ssum, g_ssum);
    cudaGetSymbolAddress((void**)&agg, g_agg);
    cudaGetSymbolAddress((void**)&row, g_row);
    cudaGetSymbolAddress((void**)&hpre, g_hpre);
    cudaGetSymbolAddress((void**)&h1, g_h1);
    cudaGetSymbolAddress((void**)&mlp, g_mlp);

    cudaFuncSetAttribute(eh_edge_gemm, cudaFuncAttributeMaxDynamicSharedMemorySize, FUS_SMEM);

    const int gN = (NN + 127) / 128;   // 391

    cudaMemsetAsync(ssum, 0, (size_t)NN * NH * sizeof(float), 0);
    cudaMemsetAsync(agg, 0, (size_t)NN * HIDD * sizeof(float), 0);
    cudaMemsetAsync(row, 0, (size_t)NN * HIDD * sizeof(float), 0);

    // Qh, Kh, Vh (fp32 A, fp16 C)
    tgemm<128, 0, false, true, false><<<dim3(gN, 1), 256>>>(x, WQ, 128, nullptr, nullptr, nullptr, nullptr, Qh, 128, NN);
    tgemm<128, 0, false, true, false><<<dim3(gN, 1), 256>>>(x, WK, 128, nullptr, nullptr, nullptr, nullptr, Kh, 128, NN);
    tgemm<128, 0, false, true, false><<<dim3(gN, 1), 256>>>(x, WV, 128, nullptr, nullptr, nullptr, nullptr, Vh, 128, NN);

    // fused: Eh GEMM + edge pass + Eo GEMM + LN1e (ce/Eh never hit gmem)
    eh_edge_gemm<<<EE / 64, 256, FUS_SMEM>>>(conn, WE, ei, Aw, Eo_w, Eo_b, ln1e_g, ln1e_b, out_e);

    // node pass -> h_pre
    node_kernel<<<(NN * 32 + 255) / 256, 256>>>(Bw, deg_coef, log_deg);

    // h1 = LN1h(x + hpre @ Ho_w + Ho_b)
    tgemm<128, 2, false, false, false><<<dim3(gN, 1), 256>>>(hpre, Ho_w, 128, Ho_b, x, ln1h_g, ln1h_b, h1, 128, NN);
    // mlp = relu(h1 @ W1 + b1); grid swapped for h1 L2 reuse
    tgemm<128, 1, false, false, true><<<dim3(2, gN), 256>>>(h1, W1, 256, b1, nullptr, nullptr, nullptr, mlp, 256, NN);
    // out_h = LN2h(h1 + mlp @ W2 + b2)
    tgemm<256, 2, false, false, false><<<dim3(gN, 1), 256>>>(mlp, W2, 128, b2, h1, ln2h_g, ln2h_b, out_h, 128, NN);
}